// round 1
// baseline (speedup 1.0000x reference)
#include <cuda_runtime.h>
#include <math.h>

// Problem constants
#define BATCH   16384
#define NNODE   4
#define DFEAT   256
#define M4      (BATCH * NNODE)        // 65536
#define M12     (BATCH * NNODE * 3)    // 196608
#define EPS     1e-5f
#define NCHUNK  256

#define EPI_NONE 0
#define EPI_RELU 1
#define EPI_SIG  2

// ---------------- static scratch (device globals, no runtime alloc) ----------
__device__ float g_XNH  [(size_t)M4  * 512];  // node hidden (post-ReLU)
__device__ float g_XNODE[(size_t)M4  * 256];  // node MLP output (sigmoid)
__device__ float g_P    [(size_t)M4  * 512];  // x_hat_src @ W0m_top
__device__ float g_Q    [(size_t)M4  * 512];  // x_hat_dst @ W0m_bot + c0m
__device__ float g_HM   [(size_t)M12 * 512];  // message hidden (post-ReLU)
__device__ float g_XMSG [(size_t)M12 * 256];  // message MLP output (sigmoid)
__device__ float g_XAGG [(size_t)M4  * 256];  // mean over 3 msgs
__device__ float g_XCAT [(size_t)M4  * 512];  // concat(node, agg)
__device__ float g_FH   [(size_t)M4  * 512];  // final hidden (post-ReLU)

__device__ float g_part [2 * NCHUNK * 512];   // reduction partials
__device__ float g_mu   [512];
__device__ float g_var  [512];
__device__ float g_sbuf [7 * 512];            // folded BN scale per stage
__device__ float g_tbuf [7 * 512];            // folded BN shift per stage
__device__ float g_zero [512];                // zero bias (static zero-init)

// ---------------- column stats: deterministic two-stage reduction -----------
__global__ void colstats_partial(const float* __restrict__ A, int M, int C,
                                 float* __restrict__ part)
{
    int c = threadIdx.x;                 // blockDim.x == C
    float sm = 0.f, ss = 0.f;
    for (int r = blockIdx.x; r < M; r += gridDim.x) {
        float v = A[(size_t)r * C + c];
        sm += v; ss += v * v;
    }
    part[(size_t)blockIdx.x * C + c]            = sm;
    part[(size_t)(NCHUNK + blockIdx.x) * C + c] = ss;
}

__global__ void colstats_final(const float* __restrict__ part, int C, int M,
                               float* __restrict__ mu, float* __restrict__ var)
{
    int c = threadIdx.x;                 // one block of C threads
    float sm = 0.f, ss = 0.f;
    for (int i = 0; i < NCHUNK; ++i) {
        sm += part[(size_t)i * C + c];
        ss += part[(size_t)(NCHUNK + i) * C + c];
    }
    float m = sm / (float)M;
    mu[c]  = m;
    var[c] = ss / (float)M - m * m;
}

// fold BN affine into (s, t): a_hat = a*s + t
__global__ void fold_bn(const float* __restrict__ g, const float* __restrict__ b,
                        const float* __restrict__ mu, const float* __restrict__ var,
                        float* __restrict__ s, float* __restrict__ t)
{
    int c = threadIdx.x;
    float sc = g[c] * rsqrtf(var[c] + EPS);
    s[c] = sc;
    t[c] = b[c] - mu[c] * sc;
}

// ---------------- SGEMM with BN-prologue on A and activation epilogue -------
// C[M,N] = epi( (A*s + t)[M,K] @ B[K,N] + bias[N] )
#define BM 128
#define BN 128
#define BK 16
#define TM 8
#define TN 8

__global__ void __launch_bounds__(256)
gemm_bn(const float* __restrict__ A, const float* __restrict__ B,
        const float* __restrict__ s, const float* __restrict__ t,
        const float* __restrict__ bias, float* __restrict__ C,
        int M, int K, int N, int epi)
{
    __shared__ float As[BK][BM];
    __shared__ float Bs[BK][BN];

    const int tid  = threadIdx.x;
    const int row0 = blockIdx.y * BM;
    const int col0 = blockIdx.x * BN;
    const int tr   = (tid >> 4) * TM;   // 0..120
    const int tc   = (tid & 15) * TN;   // 0..120

    float acc[TM][TN];
    #pragma unroll
    for (int i = 0; i < TM; ++i)
        #pragma unroll
        for (int j = 0; j < TN; ++j) acc[i][j] = 0.f;

    for (int k0 = 0; k0 < K; k0 += BK) {
        // ---- load + normalize A tile (128 x 16), transposed into As[k][m]
        #pragma unroll
        for (int p = 0; p < 2; ++p) {
            int r  = p * 64 + (tid >> 2);
            int kq = (tid & 3) * 4;
            float4 v  = *reinterpret_cast<const float4*>(&A[(size_t)(row0 + r) * K + k0 + kq]);
            float4 sv = *reinterpret_cast<const float4*>(&s[k0 + kq]);
            float4 tv = *reinterpret_cast<const float4*>(&t[k0 + kq]);
            As[kq + 0][r] = v.x * sv.x + tv.x;
            As[kq + 1][r] = v.y * sv.y + tv.y;
            As[kq + 2][r] = v.z * sv.z + tv.z;
            As[kq + 3][r] = v.w * sv.w + tv.w;
        }
        // ---- load B tile (16 x 128)
        #pragma unroll
        for (int p = 0; p < 2; ++p) {
            int kr = p * 8 + (tid >> 5);
            int nq = (tid & 31) * 4;
            *reinterpret_cast<float4*>(&Bs[kr][nq]) =
                *reinterpret_cast<const float4*>(&B[(size_t)(k0 + kr) * N + col0 + nq]);
        }
        __syncthreads();

        #pragma unroll
        for (int kk = 0; kk < BK; ++kk) {
            float a[TM], b[TN];
            #pragma unroll
            for (int i = 0; i < TM; ++i) a[i] = As[kk][tr + i];
            #pragma unroll
            for (int j = 0; j < TN; ++j) b[j] = Bs[kk][tc + j];
            #pragma unroll
            for (int i = 0; i < TM; ++i)
                #pragma unroll
                for (int j = 0; j < TN; ++j)
                    acc[i][j] += a[i] * b[j];
        }
        __syncthreads();
    }

    // ---- epilogue
    #pragma unroll
    for (int i = 0; i < TM; ++i) {
        #pragma unroll
        for (int j = 0; j < TN; j += 4) {
            float4 o;
            float* oo = &o.x;
            #pragma unroll
            for (int q = 0; q < 4; ++q) {
                float z = acc[i][j + q] + bias[col0 + tc + j + q];
                if (epi == EPI_RELU)      z = fmaxf(z, 0.f);
                else if (epi == EPI_SIG)  z = 1.f / (1.f + expf(-z));
                oo[q] = z;
            }
            *reinterpret_cast<float4*>(&C[(size_t)(row0 + tr + i) * N + col0 + tc + j]) = o;
        }
    }
}

// ---------------- H[b,i,jj] = relu(P[b,i] + Q[b,j]),  j = jj + (jj >= i) ----
__global__ void combine_pq(const float* __restrict__ P, const float* __restrict__ Q,
                           float* __restrict__ H)
{
    size_t idx = (size_t)blockIdx.x * blockDim.x + threadIdx.x; // M12*128 float4s
    int    c4  = (int)(idx & 127);
    size_t r2  = idx >> 7;
    int    jj  = (int)(r2 % 3);
    size_t bi  = r2 / 3;
    int    i   = (int)(bi & 3);
    int    j   = jj + (jj >= i);
    size_t b   = bi >> 2;

    float4 p = reinterpret_cast<const float4*>(P)[bi * 128 + c4];
    float4 q = reinterpret_cast<const float4*>(Q)[(b * 4 + j) * 128 + c4];
    float4 h;
    h.x = fmaxf(p.x + q.x, 0.f);
    h.y = fmaxf(p.y + q.y, 0.f);
    h.z = fmaxf(p.z + q.z, 0.f);
    h.w = fmaxf(p.w + q.w, 0.f);
    reinterpret_cast<float4*>(H)[idx] = h;
}

// ---------------- XAGG[bi] = mean over jj of XMSG[bi*3+jj] ------------------
__global__ void avg3(const float* __restrict__ XMSG, float* __restrict__ XAGG)
{
    size_t idx = (size_t)blockIdx.x * blockDim.x + threadIdx.x; // M4*64 float4s
    int    c4  = (int)(idx & 63);
    size_t bi  = idx >> 6;
    const float4* m = reinterpret_cast<const float4*>(XMSG);
    float4 a = m[(bi * 3 + 0) * 64 + c4];
    float4 b = m[(bi * 3 + 1) * 64 + c4];
    float4 c = m[(bi * 3 + 2) * 64 + c4];
    const float inv3 = 1.f / 3.f;
    float4 o;
    o.x = (a.x + b.x + c.x) * inv3;
    o.y = (a.y + b.y + c.y) * inv3;
    o.z = (a.z + b.z + c.z) * inv3;
    o.w = (a.w + b.w + c.w) * inv3;
    reinterpret_cast<float4*>(XAGG)[idx] = o;
}

// ---------------- XCAT[r] = [XNODE[r], XAGG[r]] -----------------------------
__global__ void concat2(const float* __restrict__ X1, const float* __restrict__ X2,
                        float* __restrict__ O)
{
    size_t idx = (size_t)blockIdx.x * blockDim.x + threadIdx.x; // M4*128 float4s
    int    c4  = (int)(idx & 127);
    size_t r   = idx >> 7;
    float4 v = (c4 < 64)
             ? reinterpret_cast<const float4*>(X1)[r * 64 + c4]
             : reinterpret_cast<const float4*>(X2)[r * 64 + (c4 - 64)];
    reinterpret_cast<float4*>(O)[idx] = v;
}

// ---------------- launch ------------------------------------------------------
static inline float* sym(const void* symbol)
{
    void* p = nullptr;
    cudaGetSymbolAddress(&p, symbol);
    return (float*)p;
}

extern "C" void kernel_launch(void* const* d_in, const int* in_sizes, int n_in,
                              void* d_out, int out_size)
{
    const float* x   = (const float*)d_in[0];
    const float* ng0 = (const float*)d_in[1];
    const float* nb0 = (const float*)d_in[2];
    const float* nW0 = (const float*)d_in[3];
    const float* nc0 = (const float*)d_in[4];
    const float* ng1 = (const float*)d_in[5];
    const float* nb1 = (const float*)d_in[6];
    const float* nW1 = (const float*)d_in[7];
    const float* nc1 = (const float*)d_in[8];
    const float* mg0 = (const float*)d_in[9];
    const float* mb0 = (const float*)d_in[10];
    const float* mW0 = (const float*)d_in[11];
    const float* mc0 = (const float*)d_in[12];
    const float* mg1 = (const float*)d_in[13];
    const float* mb1 = (const float*)d_in[14];
    const float* mW1 = (const float*)d_in[15];
    const float* mc1 = (const float*)d_in[16];
    const float* fg0 = (const float*)d_in[17];
    const float* fb0 = (const float*)d_in[18];
    const float* fW0 = (const float*)d_in[19];
    const float* fc0 = (const float*)d_in[20];
    const float* fg1 = (const float*)d_in[21];
    const float* fb1 = (const float*)d_in[22];
    const float* fW1 = (const float*)d_in[23];
    const float* fc1 = (const float*)d_in[24];
    float* out = (float*)d_out;

    float* XNH  = sym(g_XNH);
    float* XNODE= sym(g_XNODE);
    float* P    = sym(g_P);
    float* Q    = sym(g_Q);
    float* HM   = sym(g_HM);
    float* XMSG = sym(g_XMSG);
    float* XAGG = sym(g_XAGG);
    float* XCAT = sym(g_XCAT);
    float* FH   = sym(g_FH);
    float* part = sym(g_part);
    float* mu   = sym(g_mu);
    float* var  = sym(g_var);
    float* S    = sym(g_sbuf);
    float* T    = sym(g_tbuf);
    float* zero = sym(g_zero);

    float *s_n0 = S + 0*512, *t_n0 = T + 0*512;
    float *s_n1 = S + 1*512, *t_n1 = T + 1*512;
    float *s_p  = S + 2*512, *t_p  = T + 2*512;
    float *s_q  = S + 3*512, *t_q  = T + 3*512;
    float *s_m1 = S + 4*512, *t_m1 = T + 4*512;
    float *s_f0 = S + 5*512, *t_f0 = T + 5*512;
    float *s_f1 = S + 6*512, *t_f1 = T + 6*512;

    // ---- input stats (shared by node MLP and both halves of msg MLP) ----
    colstats_partial<<<NCHUNK, 256>>>(x, M4, 256, part);
    colstats_final  <<<1, 256>>>(part, 256, M4, mu, var);
    fold_bn<<<1, 256>>>(ng0,       nb0,       mu, var, s_n0, t_n0);
    fold_bn<<<1, 256>>>(mg0,       mb0,       mu, var, s_p,  t_p);
    fold_bn<<<1, 256>>>(mg0 + 256, mb0 + 256, mu, var, s_q,  t_q);

    // ---- node MLP ----
    gemm_bn<<<dim3(512/BN, M4/BM), 256>>>(x, nW0, s_n0, t_n0, nc0, XNH, M4, 256, 512, EPI_RELU);
    colstats_partial<<<NCHUNK, 512>>>(XNH, M4, 512, part);
    colstats_final  <<<1, 512>>>(part, 512, M4, mu, var);
    fold_bn<<<1, 512>>>(ng1, nb1, mu, var, s_n1, t_n1);
    gemm_bn<<<dim3(256/BN, M4/BM), 256>>>(XNH, nW1, s_n1, t_n1, nc1, XNODE, M4, 512, 256, EPI_SIG);

    // ---- msg MLP layer-0 via P/Q factorization ----
    gemm_bn<<<dim3(512/BN, M4/BM), 256>>>(x, mW0,             s_p, t_p, zero, P, M4, 256, 512, EPI_NONE);
    gemm_bn<<<dim3(512/BN, M4/BM), 256>>>(x, mW0 + 256 * 512, s_q, t_q, mc0,  Q, M4, 256, 512, EPI_NONE);
    combine_pq<<<(size_t)M12 * 128 / 256, 256>>>(P, Q, HM);

    // ---- msg MLP layer-1 ----
    colstats_partial<<<NCHUNK, 512>>>(HM, M12, 512, part);
    colstats_final  <<<1, 512>>>(part, 512, M12, mu, var);
    fold_bn<<<1, 512>>>(mg1, mb1, mu, var, s_m1, t_m1);
    gemm_bn<<<dim3(256/BN, M12/BM), 256>>>(HM, mW1, s_m1, t_m1, mc1, XMSG, M12, 512, 256, EPI_SIG);
    avg3<<<(size_t)M4 * 64 / 256, 256>>>(XMSG, XAGG);

    // ---- final MLP ----
    concat2<<<(size_t)M4 * 128 / 256, 256>>>(XNODE, XAGG, XCAT);
    colstats_partial<<<NCHUNK, 512>>>(XCAT, M4, 512, part);
    colstats_final  <<<1, 512>>>(part, 512, M4, mu, var);
    fold_bn<<<1, 512>>>(fg0, fb0, mu, var, s_f0, t_f0);
    gemm_bn<<<dim3(512/BN, M4/BM), 256>>>(XCAT, fW0, s_f0, t_f0, fc0, FH, M4, 512, 512, EPI_RELU);
    colstats_partial<<<NCHUNK, 512>>>(FH, M4, 512, part);
    colstats_final  <<<1, 512>>>(part, 512, M4, mu, var);
    fold_bn<<<1, 512>>>(fg1, fb1, mu, var, s_f1, t_f1);
    gemm_bn<<<dim3(256/BN, M4/BM), 256>>>(FH, fW1, s_f1, t_f1, fc1, out, M4, 512, 256, EPI_SIG);
}

// round 3
// speedup vs baseline: 2.2529x; 2.2529x over previous
#include <cuda_runtime.h>
#include <cstdint>
#include <math.h>

// ---------------- problem constants ----------------
#define BATCH   16384
#define M4      65536                 // BATCH*4
#define M12     196608                // BATCH*12
#define EPS     1e-5f
#define NCHUNK  256

#define APAD 36    // A smem row stride (floats), 32-wide k tile + pad
#define BPAD 132   // B smem row stride (floats), 128-wide n tile + pad

// ---------------- PTX helpers (all plain sm_80+ PTX, no 'a' features) -------
__device__ __forceinline__ void cp16(uint32_t dst, const void* src) {
    asm volatile("cp.async.cg.shared.global [%0], [%1], 16;" :: "r"(dst), "l"(src));
}
__device__ __forceinline__ uint32_t smem_u32(const void* p) {
    uint32_t a;
    asm("{ .reg .u64 t; cvta.to.shared.u64 t, %1; cvt.u32.u64 %0, t; }" : "=r"(a) : "l"(p));
    return a;
}
__device__ __forceinline__ uint32_t f2tf(float f) {
    uint32_t u;
    asm("cvt.rna.tf32.f32 %0, %1;" : "=r"(u) : "f"(f));
    return u;
}
__device__ __forceinline__ void mma8(float* c, const uint32_t* a, const uint32_t* b) {
    asm volatile(
        "mma.sync.aligned.m16n8k8.row.col.f32.tf32.tf32.f32 "
        "{%0,%1,%2,%3},{%4,%5,%6,%7},{%8,%9},{%0,%1,%2,%3};"
        : "+f"(c[0]), "+f"(c[1]), "+f"(c[2]), "+f"(c[3])
        : "r"(a[0]), "r"(a[1]), "r"(a[2]), "r"(a[3]), "r"(b[0]), "r"(b[1]));
}

// ---------------- static scratch ----------------
__device__ float g_XNH  [(size_t)M4  * 512];
__device__ float g_XNODE[(size_t)M4  * 256];
__device__ float g_P    [(size_t)M4  * 512];
__device__ float g_Q    [(size_t)M4  * 512];
__device__ float g_XMSG [(size_t)M12 * 256];
__device__ float g_XAGG [(size_t)M4  * 256];
__device__ float g_FH   [(size_t)M4  * 512];

__device__ float g_part [2 * NCHUNK * 512];
__device__ float g_mu   [512];
__device__ float g_var  [512];
__device__ float g_sbuf [7 * 512];
__device__ float g_tbuf [7 * 512];
__device__ float g_zero [512];

// ---------------- small kernels ----------------
__global__ void colstats_partial(const float* __restrict__ A, int M, int C,
                                 float* __restrict__ part)
{
    int c = threadIdx.x;
    float sm = 0.f, ss = 0.f;
    for (int r = blockIdx.x; r < M; r += gridDim.x) {
        float v = A[(size_t)r * C + c];
        sm += v; ss += v * v;
    }
    part[(size_t)blockIdx.x * C + c]            = sm;
    part[(size_t)(NCHUNK + blockIdx.x) * C + c] = ss;
}

__global__ void colstats_final(const float* __restrict__ part, int C, int M,
                               float* __restrict__ mu, float* __restrict__ var)
{
    int c = threadIdx.x;
    float sm = 0.f, ss = 0.f;
    for (int i = 0; i < NCHUNK; ++i) {
        sm += part[(size_t)i * C + c];
        ss += part[(size_t)(NCHUNK + i) * C + c];
    }
    float m = sm / (float)M;
    mu[c]  = m;
    var[c] = ss / (float)M - m * m;
}

// stats of relu(P[b,i]+Q[b,j]) over all ordered pairs i!=j, HM never materialized
__global__ void pqstats_partial(const float* __restrict__ P, const float* __restrict__ Q,
                                float* __restrict__ part)
{
    int c = threadIdx.x;  // 512
    float sm = 0.f, ss = 0.f;
    for (int b = blockIdx.x; b < BATCH; b += gridDim.x) {
        float pv[4], qv[4];
        #pragma unroll
        for (int i = 0; i < 4; ++i) {
            pv[i] = P[((size_t)b * 4 + i) * 512 + c];
            qv[i] = Q[((size_t)b * 4 + i) * 512 + c];
        }
        #pragma unroll
        for (int i = 0; i < 4; ++i)
            #pragma unroll
            for (int j = 0; j < 4; ++j)
                if (i != j) {
                    float v = fmaxf(pv[i] + qv[j], 0.f);
                    sm += v; ss += v * v;
                }
    }
    part[(size_t)blockIdx.x * 512 + c]            = sm;
    part[(size_t)(NCHUNK + blockIdx.x) * 512 + c] = ss;
}

__global__ void fold_bn(const float* __restrict__ g, const float* __restrict__ b,
                        const float* __restrict__ mu, const float* __restrict__ var,
                        float* __restrict__ s, float* __restrict__ t)
{
    int c = threadIdx.x;
    float sc = g[c] * rsqrtf(var[c] + EPS);
    s[c] = sc;
    t[c] = b[c] - mu[c] * sc;
}

__global__ void avg3(const float* __restrict__ XMSG, float* __restrict__ XAGG)
{
    size_t idx = (size_t)blockIdx.x * blockDim.x + threadIdx.x; // M4*64 float4s
    int    c4  = (int)(idx & 63);
    size_t bi  = idx >> 6;
    const float4* m = reinterpret_cast<const float4*>(XMSG);
    float4 a = m[(bi * 3 + 0) * 64 + c4];
    float4 b = m[(bi * 3 + 1) * 64 + c4];
    float4 c = m[(bi * 3 + 2) * 64 + c4];
    const float inv3 = 1.f / 3.f;
    float4 o;
    o.x = (a.x + b.x + c.x) * inv3;
    o.y = (a.y + b.y + c.y) * inv3;
    o.z = (a.z + b.z + c.z) * inv3;
    o.w = (a.w + b.w + c.w) * inv3;
    reinterpret_cast<float4*>(XAGG)[idx] = o;
}

// ---------------- tf32 mma.sync GEMM -----------------------------------------
// C[M,N] = epi( (Asrc*s + t)[M,K] @ W[K,N] + bias )
// AMODE 0: Asrc = A  (row-major [M,K])
// AMODE 1: Asrc[r,k] = relu(P[b*4+i,k] + Q[b*4+j,k]), r=(b,i,jj), j=jj+(jj>=i); K=512
// AMODE 2: Asrc[r,k] = k<256 ? A[r,k] : A2[r,k-256]  (A,A2 are [M,256]); K=512
// EPI 0: none, 1: relu, 2: sigmoid
// CTA 128x128, 128 threads (4 warps, 2x2 grid of 64x64 warp tiles), K chunks of 32.

template<int AMODE>
__device__ __forceinline__ void stageA(float* smAbuf, uint32_t uAbuf,
                                       const float* __restrict__ A,
                                       const float* __restrict__ A2,
                                       int row0, int kbase, int K, int tid)
{
    if (AMODE != 1) {
        #pragma unroll
        for (int p = 0; p < 8; ++p) {
            int lin = p * 128 + tid;
            int row = lin >> 3;
            int f4  = lin & 7;
            int gk  = kbase + f4 * 4;
            const float* src;
            if (AMODE == 0) src = &A[(size_t)(row0 + row) * K + gk];
            else src = (gk < 256) ? &A [(size_t)(row0 + row) * 256 + gk]
                                  : &A2[(size_t)(row0 + row) * 256 + gk - 256];
            cp16(uAbuf + (uint32_t)(row * APAD + f4 * 4) * 4u, src);
        }
    } else {
        #pragma unroll
        for (int p = 0; p < 8; ++p) {
            int lin = p * 128 + tid;
            int row = lin >> 3;
            int f4  = lin & 7;
            int gr  = row0 + row;
            int b   = gr / 12;
            int rem = gr - b * 12;
            int i   = rem / 3;
            int jj  = rem - i * 3;
            int j   = jj + (jj >= i);
            int gk  = kbase + f4 * 4;
            float4 pv = *reinterpret_cast<const float4*>(&A [((size_t)b * 4 + i) * 512 + gk]);
            float4 qv = *reinterpret_cast<const float4*>(&A2[((size_t)b * 4 + j) * 512 + gk]);
            float4 v;
            v.x = fmaxf(pv.x + qv.x, 0.f);
            v.y = fmaxf(pv.y + qv.y, 0.f);
            v.z = fmaxf(pv.z + qv.z, 0.f);
            v.w = fmaxf(pv.w + qv.w, 0.f);
            *reinterpret_cast<float4*>(&smAbuf[row * APAD + f4 * 4]) = v;
        }
    }
}

__device__ __forceinline__ void stageB(uint32_t uBbuf, const float* __restrict__ W,
                                       int col0, int kbase, int N, int tid)
{
    #pragma unroll
    for (int p = 0; p < 8; ++p) {
        int lin = p * 128 + tid;
        int k   = lin >> 5;          // 0..31
        int f4  = lin & 31;          // 0..31 (128 cols)
        cp16(uBbuf + (uint32_t)(k * BPAD + f4 * 4) * 4u,
             &W[(size_t)(kbase + k) * N + col0 + f4 * 4]);
    }
}

template<int AMODE, int EPI>
__global__ void __launch_bounds__(128)
gemm_mma(const float* __restrict__ A, const float* __restrict__ A2,
         const float* __restrict__ W,
         const float* __restrict__ s, const float* __restrict__ t,
         const float* __restrict__ bias, float* __restrict__ C,
         int K, int N)
{
    extern __shared__ float sm[];
    float* smA = sm;                              // 2 * 128 * APAD
    float* smB = smA + 2 * 128 * APAD;            // 2 * 32 * BPAD
    float* smS = smB + 2 * 32 * BPAD;             // 512
    float* smT = smS + 512;                       // 512
    const uint32_t uA = smem_u32(smA);
    const uint32_t uB = smem_u32(smB);

    const int tid  = threadIdx.x;
    const int lane = tid & 31;
    const int warp = tid >> 5;
    const int wm   = warp >> 1;
    const int wn   = warp & 1;
    const int row0 = blockIdx.y * 128;
    const int col0 = blockIdx.x * 128;

    for (int i = tid; i < K; i += 128) { smS[i] = s[i]; smT[i] = t[i]; }

    float acc[4][8][4];
    #pragma unroll
    for (int a = 0; a < 4; ++a)
        #pragma unroll
        for (int b = 0; b < 8; ++b)
            #pragma unroll
            for (int q = 0; q < 4; ++q) acc[a][b][q] = 0.f;

    const int NC = K >> 5;
    stageA<AMODE>(smA, uA, A, A2, row0, 0, K, tid);
    stageB(uB, W, col0, 0, N, tid);
    asm volatile("cp.async.commit_group;");

    for (int c = 0; c < NC; ++c) {
        const int b = c & 1;
        float* cA = smA + b * 128 * APAD;
        float* cB = smB + b * 32 * BPAD;
        if (c + 1 < NC) {
            stageA<AMODE>(smA + (1 - b) * 128 * APAD,
                          uA + (uint32_t)((1 - b) * 128 * APAD) * 4u,
                          A, A2, row0, (c + 1) * 32, K, tid);
            stageB(uB + (uint32_t)((1 - b) * 32 * BPAD) * 4u, W, col0, (c + 1) * 32, N, tid);
            asm volatile("cp.async.commit_group;");
            asm volatile("cp.async.wait_group 1;");
        } else {
            asm volatile("cp.async.wait_group 0;");
        }
        __syncthreads();

        const int kb = c * 32;
        float sk[8], tk[8];
        #pragma unroll
        for (int j = 0; j < 8; ++j) {
            sk[j] = smS[kb + j * 4 + (lane & 3)];
            tk[j] = smT[kb + j * 4 + (lane & 3)];
        }

        #pragma unroll
        for (int ks = 0; ks < 4; ++ks) {
            const int kc = ks * 8 + (lane & 3);
            const float s0 = sk[2 * ks],     t0 = tk[2 * ks];
            const float s1 = sk[2 * ks + 1], t1 = tk[2 * ks + 1];

            uint32_t af[4][4];
            #pragma unroll
            for (int mt = 0; mt < 4; ++mt) {
                int m = wm * 64 + mt * 16 + (lane >> 2);
                af[mt][0] = f2tf(cA[m       * APAD + kc    ] * s0 + t0);
                af[mt][1] = f2tf(cA[(m + 8) * APAD + kc    ] * s0 + t0);
                af[mt][2] = f2tf(cA[m       * APAD + kc + 4] * s1 + t1);
                af[mt][3] = f2tf(cA[(m + 8) * APAD + kc + 4] * s1 + t1);
            }
            uint32_t bf[8][2];
            #pragma unroll
            for (int nt = 0; nt < 8; ++nt) {
                int n = wn * 64 + nt * 8 + (lane >> 2);
                bf[nt][0] = f2tf(cB[kc       * BPAD + n]);
                bf[nt][1] = f2tf(cB[(kc + 4) * BPAD + n]);
            }
            #pragma unroll
            for (int mt = 0; mt < 4; ++mt)
                #pragma unroll
                for (int nt = 0; nt < 8; ++nt)
                    mma8(acc[mt][nt], af[mt], bf[nt]);
        }
        __syncthreads();
    }

    // ---- epilogue
    #pragma unroll
    for (int mt = 0; mt < 4; ++mt) {
        int r0 = row0 + wm * 64 + mt * 16 + (lane >> 2);
        #pragma unroll
        for (int nt = 0; nt < 8; ++nt) {
            int col = col0 + wn * 64 + nt * 8 + (lane & 3) * 2;
            float b0 = bias[col], b1 = bias[col + 1];
            float v0 = acc[mt][nt][0] + b0;
            float v1 = acc[mt][nt][1] + b1;
            float v2 = acc[mt][nt][2] + b0;
            float v3 = acc[mt][nt][3] + b1;
            if (EPI == 1) {
                v0 = fmaxf(v0, 0.f); v1 = fmaxf(v1, 0.f);
                v2 = fmaxf(v2, 0.f); v3 = fmaxf(v3, 0.f);
            } else if (EPI == 2) {
                v0 = 1.f / (1.f + expf(-v0));
                v1 = 1.f / (1.f + expf(-v1));
                v2 = 1.f / (1.f + expf(-v2));
                v3 = 1.f / (1.f + expf(-v3));
            }
            *reinterpret_cast<float2*>(&C[(size_t)r0 * N + col])       = make_float2(v0, v1);
            *reinterpret_cast<float2*>(&C[(size_t)(r0 + 8) * N + col]) = make_float2(v2, v3);
        }
    }
}

// ---------------- launch ----------------
static inline float* sym(const void* symbol)
{
    void* p = nullptr;
    cudaGetSymbolAddress(&p, symbol);
    return (float*)p;
}

#define SHM_BYTES ((2*128*APAD + 2*32*BPAD + 1024) * 4)

extern "C" void kernel_launch(void* const* d_in, const int* in_sizes, int n_in,
                              void* d_out, int out_size)
{
    const float* x   = (const float*)d_in[0];
    const float* ng0 = (const float*)d_in[1];
    const float* nb0 = (const float*)d_in[2];
    const float* nW0 = (const float*)d_in[3];
    const float* nc0 = (const float*)d_in[4];
    const float* ng1 = (const float*)d_in[5];
    const float* nb1 = (const float*)d_in[6];
    const float* nW1 = (const float*)d_in[7];
    const float* nc1 = (const float*)d_in[8];
    const float* mg0 = (const float*)d_in[9];
    const float* mb0 = (const float*)d_in[10];
    const float* mW0 = (const float*)d_in[11];
    const float* mc0 = (const float*)d_in[12];
    const float* mg1 = (const float*)d_in[13];
    const float* mb1 = (const float*)d_in[14];
    const float* mW1 = (const float*)d_in[15];
    const float* mc1 = (const float*)d_in[16];
    const float* fg0 = (const float*)d_in[17];
    const float* fb0 = (const float*)d_in[18];
    const float* fW0 = (const float*)d_in[19];
    const float* fc0 = (const float*)d_in[20];
    const float* fg1 = (const float*)d_in[21];
    const float* fb1 = (const float*)d_in[22];
    const float* fW1 = (const float*)d_in[23];
    const float* fc1 = (const float*)d_in[24];
    float* out = (float*)d_out;

    float* XNH   = sym(g_XNH);
    float* XNODE = sym(g_XNODE);
    float* P     = sym(g_P);
    float* Q     = sym(g_Q);
    float* XMSG  = sym(g_XMSG);
    float* XAGG  = sym(g_XAGG);
    float* FH    = sym(g_FH);
    float* part  = sym(g_part);
    float* mu    = sym(g_mu);
    float* var   = sym(g_var);
    float* S     = sym(g_sbuf);
    float* T     = sym(g_tbuf);
    float* zero  = sym(g_zero);

    float *s_n0 = S + 0*512, *t_n0 = T + 0*512;
    float *s_n1 = S + 1*512, *t_n1 = T + 1*512;
    float *s_p  = S + 2*512, *t_p  = T + 2*512;
    float *s_q  = S + 3*512, *t_q  = T + 3*512;
    float *s_m1 = S + 4*512, *t_m1 = T + 4*512;
    float *s_f0 = S + 5*512, *t_f0 = T + 5*512;
    float *s_f1 = S + 6*512, *t_f1 = T + 6*512;

    cudaFuncSetAttribute(gemm_mma<0,1>, cudaFuncAttributeMaxDynamicSharedMemorySize, SHM_BYTES);
    cudaFuncSetAttribute(gemm_mma<0,0>, cudaFuncAttributeMaxDynamicSharedMemorySize, SHM_BYTES);
    cudaFuncSetAttribute(gemm_mma<0,2>, cudaFuncAttributeMaxDynamicSharedMemorySize, SHM_BYTES);
    cudaFuncSetAttribute(gemm_mma<1,2>, cudaFuncAttributeMaxDynamicSharedMemorySize, SHM_BYTES);
    cudaFuncSetAttribute(gemm_mma<2,1>, cudaFuncAttributeMaxDynamicSharedMemorySize, SHM_BYTES);

    // ---- input stats (shared by node MLP and msg MLP halves)
    colstats_partial<<<NCHUNK, 256>>>(x, M4, 256, part);
    colstats_final  <<<1, 256>>>(part, 256, M4, mu, var);
    fold_bn<<<1, 256>>>(ng0,       nb0,       mu, var, s_n0, t_n0);
    fold_bn<<<1, 256>>>(mg0,       mb0,       mu, var, s_p,  t_p);
    fold_bn<<<1, 256>>>(mg0 + 256, mb0 + 256, mu, var, s_q,  t_q);

    // ---- node MLP
    gemm_mma<0,1><<<dim3(4, M4/128), 128, SHM_BYTES>>>(x, nullptr, nW0, s_n0, t_n0, nc0, XNH, 256, 512);
    colstats_partial<<<NCHUNK, 512>>>(XNH, M4, 512, part);
    colstats_final  <<<1, 512>>>(part, 512, M4, mu, var);
    fold_bn<<<1, 512>>>(ng1, nb1, mu, var, s_n1, t_n1);
    gemm_mma<0,2><<<dim3(2, M4/128), 128, SHM_BYTES>>>(XNH, nullptr, nW1, s_n1, t_n1, nc1, XNODE, 512, 256);

    // ---- msg MLP layer-0 via P/Q factorization
    gemm_mma<0,0><<<dim3(4, M4/128), 128, SHM_BYTES>>>(x, nullptr, mW0,             s_p, t_p, zero, P, 256, 512);
    gemm_mma<0,0><<<dim3(4, M4/128), 128, SHM_BYTES>>>(x, nullptr, mW0 + 256 * 512, s_q, t_q, mc0,  Q, 256, 512);

    // ---- msg hidden stats (from P,Q; HM never materialized)
    pqstats_partial<<<NCHUNK, 512>>>(P, Q, part);
    colstats_final <<<1, 512>>>(part, 512, M12, mu, var);
    fold_bn<<<1, 512>>>(mg1, mb1, mu, var, s_m1, t_m1);

    // ---- msg MLP layer-1, A = relu(P+Q) on the fly
    gemm_mma<1,2><<<dim3(2, M12/128), 128, SHM_BYTES>>>(P, Q, mW1, s_m1, t_m1, mc1, XMSG, 512, 256);
    avg3<<<(size_t)M4 * 64 / 256, 256>>>(XMSG, XAGG);

    // ---- final MLP, A = concat(XNODE, XAGG) on the fly
    colstats_partial<<<NCHUNK, 256>>>(XNODE, M4, 256, part);
    colstats_final  <<<1, 256>>>(part, 256, M4, mu, var);
    colstats_partial<<<NCHUNK, 256>>>(XAGG, M4, 256, part);
    colstats_final  <<<1, 256>>>(part, 256, M4, mu + 256, var + 256);
    fold_bn<<<1, 512>>>(fg0, fb0, mu, var, s_f0, t_f0);
    gemm_mma<2,1><<<dim3(4, M4/128), 128, SHM_BYTES>>>(XNODE, XAGG, fW0, s_f0, t_f0, fc0, FH, 512, 512);
    colstats_partial<<<NCHUNK, 512>>>(FH, M4, 512, part);
    colstats_final  <<<1, 512>>>(part, 512, M4, mu, var);
    fold_bn<<<1, 512>>>(fg1, fb1, mu, var, s_f1, t_f1);
    gemm_mma<0,2><<<dim3(2, M4/128), 128, SHM_BYTES>>>(FH, nullptr, fW1, s_f1, t_f1, fc1, out, 512, 256);
}

// round 5
// speedup vs baseline: 2.9914x; 1.3278x over previous
#include <cuda_runtime.h>
#include <cuda_fp16.h>
#include <cstdint>
#include <math.h>

// ---------------- problem constants ----------------
#define BATCH   16384
#define M4      65536
#define M12     196608
#define EPS     1e-5f
#define NCHUNK  256

#define APADH 72    // A smem row stride in halves (64-k tile + 8)  -> 144B, 16B-mult
#define BPADH 264   // B smem row stride in halves (256-n tile + 8) -> 528B, 16B-mult

// ---------------- PTX helpers (plain sm_80+ PTX only) ----------------
__device__ __forceinline__ void cp16(uint32_t dst, const void* src) {
    asm volatile("cp.async.cg.shared.global [%0], [%1], 16;" :: "r"(dst), "l"(src));
}
__device__ __forceinline__ uint32_t smem_u32(const void* p) {
    uint32_t a;
    asm("{ .reg .u64 t; cvta.to.shared.u64 t, %1; cvt.u32.u64 %0, t; }" : "=r"(a) : "l"(p));
    return a;
}
__device__ __forceinline__ void mma16816(float* c, const uint32_t* a, const uint32_t* b) {
    asm volatile(
        "mma.sync.aligned.m16n8k16.row.col.f32.f16.f16.f32 "
        "{%0,%1,%2,%3},{%4,%5,%6,%7},{%8,%9},{%0,%1,%2,%3};"
        : "+f"(c[0]), "+f"(c[1]), "+f"(c[2]), "+f"(c[3])
        : "r"(a[0]), "r"(a[1]), "r"(a[2]), "r"(a[3]), "r"(b[0]), "r"(b[1]));
}
__device__ __forceinline__ void ldmx4(uint32_t* r, uint32_t addr) {
    asm volatile("ldmatrix.sync.aligned.m8n8.x4.shared.b16 {%0,%1,%2,%3}, [%4];"
        : "=r"(r[0]), "=r"(r[1]), "=r"(r[2]), "=r"(r[3]) : "r"(addr));
}
__device__ __forceinline__ void ldmx4t(uint32_t* r, uint32_t addr) {
    asm volatile("ldmatrix.sync.aligned.m8n8.x4.trans.shared.b16 {%0,%1,%2,%3}, [%4];"
        : "=r"(r[0]), "=r"(r[1]), "=r"(r[2]), "=r"(r[3]) : "r"(addr));
}

// ---------------- static scratch ----------------
__device__ __half g_xh    [(size_t)M4  * 256];
__device__ __half g_XNH   [(size_t)M4  * 512];
__device__ __half g_XNODE [(size_t)M4  * 256];
__device__ __half g_P     [(size_t)M4  * 512];
__device__ __half g_Q     [(size_t)M4  * 512];
__device__ float  g_XMSG  [(size_t)M12 * 256];
__device__ __half g_XAGG  [(size_t)M4  * 256];
__device__ __half g_FH    [(size_t)M4  * 512];

__device__ float  g_part  [2 * NCHUNK * 512];
__device__ float  g_mu    [512];
__device__ float  g_var   [512];
__device__ float  g_sbuf  [7 * 512];
__device__ float  g_tbuf  [7 * 512];
__device__ float  g_zero  [512];
__device__ float  g_bias  [7 * 512];          // folded biases

// folded half weights
__device__ __half g_Whn0 [256 * 512];
__device__ __half g_Whn1 [512 * 256];
__device__ __half g_Whp  [256 * 512];
__device__ __half g_Whq  [256 * 512];
__device__ __half g_Whm1 [512 * 256];
__device__ __half g_Whf0 [512 * 512];
__device__ __half g_Whf1 [512 * 256];

// ---------------- small kernels ----------------
__global__ void cvt_x(const float* __restrict__ x, __half* __restrict__ xh)
{
    size_t i = ((size_t)blockIdx.x * blockDim.x + threadIdx.x) * 4;
    float4 v = *reinterpret_cast<const float4*>(&x[i]);
    __half2 h0 = __floats2half2_rn(v.x, v.y);
    __half2 h1 = __floats2half2_rn(v.z, v.w);
    *reinterpret_cast<__half2*>(&xh[i])     = h0;
    *reinterpret_cast<__half2*>(&xh[i + 2]) = h1;
}

__global__ void colstats_partial_f(const float* __restrict__ A, int M, int C,
                                   float* __restrict__ part)
{
    int c = threadIdx.x;
    float sm = 0.f, ss = 0.f;
    for (int r = blockIdx.x; r < M; r += gridDim.x) {
        float v = A[(size_t)r * C + c];
        sm += v; ss += v * v;
    }
    part[(size_t)blockIdx.x * C + c]            = sm;
    part[(size_t)(NCHUNK + blockIdx.x) * C + c] = ss;
}

__global__ void colstats_partial_h(const __half* __restrict__ A, int M, int C,
                                   float* __restrict__ part)
{
    int c = threadIdx.x;
    float sm = 0.f, ss = 0.f;
    for (int r = blockIdx.x; r < M; r += gridDim.x) {
        float v = __half2float(A[(size_t)r * C + c]);
        sm += v; ss += v * v;
    }
    part[(size_t)blockIdx.x * C + c]            = sm;
    part[(size_t)(NCHUNK + blockIdx.x) * C + c] = ss;
}

__global__ void colstats_final(const float* __restrict__ part, int C, int M,
                               float* __restrict__ mu, float* __restrict__ var)
{
    int c = threadIdx.x;
    float sm = 0.f, ss = 0.f;
    for (int i = 0; i < NCHUNK; ++i) {
        sm += part[(size_t)i * C + c];
        ss += part[(size_t)(NCHUNK + i) * C + c];
    }
    float m = sm / (float)M;
    mu[c]  = m;
    var[c] = ss / (float)M - m * m;
}

__global__ void pqstats_partial(const __half* __restrict__ P, const __half* __restrict__ Q,
                                float* __restrict__ part)
{
    int c = threadIdx.x;  // 512
    float sm = 0.f, ss = 0.f;
    for (int b = blockIdx.x; b < BATCH; b += gridDim.x) {
        float pv[4], qv[4];
        #pragma unroll
        for (int i = 0; i < 4; ++i) {
            pv[i] = __half2float(P[((size_t)b * 4 + i) * 512 + c]);
            qv[i] = __half2float(Q[((size_t)b * 4 + i) * 512 + c]);
        }
        #pragma unroll
        for (int i = 0; i < 4; ++i)
            #pragma unroll
            for (int j = 0; j < 4; ++j)
                if (i != j) {
                    float v = fmaxf(pv[i] + qv[j], 0.f);
                    sm += v; ss += v * v;
                }
    }
    part[(size_t)blockIdx.x * 512 + c]            = sm;
    part[(size_t)(NCHUNK + blockIdx.x) * 512 + c] = ss;
}

__global__ void fold_bn(const float* __restrict__ g, const float* __restrict__ b,
                        const float* __restrict__ mu, const float* __restrict__ var,
                        float* __restrict__ s, float* __restrict__ t)
{
    int c = threadIdx.x;
    float sc = g[c] * rsqrtf(var[c] + EPS);
    s[c] = sc;
    t[c] = b[c] - mu[c] * sc;
}

// Wh[k][n] = half(W[k][n] * s[k])
__global__ void fold_w(const float* __restrict__ W, const float* __restrict__ s,
                       __half* __restrict__ Wh, int N)
{
    int idx = blockIdx.x * blockDim.x + threadIdx.x;
    int k = idx / N;
    Wh[idx] = __float2half(W[idx] * s[k]);
}

// bout[n] = c[n] + sum_k t[k]*W[k][n]
__global__ void fold_bias(const float* __restrict__ W, const float* __restrict__ t,
                          const float* __restrict__ c, float* __restrict__ bout,
                          int K, int N)
{
    int n = blockIdx.x * blockDim.x + threadIdx.x;
    if (n >= N) return;
    float a = c[n];
    for (int k = 0; k < K; ++k) a += t[k] * W[(size_t)k * N + n];
    bout[n] = a;
}

__global__ void avg3(const float* __restrict__ XMSG, __half* __restrict__ XAGG)
{
    size_t idx = (size_t)blockIdx.x * blockDim.x + threadIdx.x; // M4*64 groups of 4
    int    c4  = (int)(idx & 63);
    size_t bi  = idx >> 6;
    const float4* m = reinterpret_cast<const float4*>(XMSG);
    float4 a = m[(bi * 3 + 0) * 64 + c4];
    float4 b = m[(bi * 3 + 1) * 64 + c4];
    float4 c = m[(bi * 3 + 2) * 64 + c4];
    const float inv3 = 1.f / 3.f;
    __half2 h0 = __floats2half2_rn((a.x + b.x + c.x) * inv3, (a.y + b.y + c.y) * inv3);
    __half2 h1 = __floats2half2_rn((a.z + b.z + c.z) * inv3, (a.w + b.w + c.w) * inv3);
    *reinterpret_cast<__half2*>(&XAGG[bi * 256 + c4 * 4])     = h0;
    *reinterpret_cast<__half2*>(&XAGG[bi * 256 + c4 * 4 + 2]) = h1;
}

// ---------------- fp16 mma GEMM ----------------------------------------------
// C[M,N] = epi( A[M,K] @ Wh[K,N] + bias )      (BN already folded into Wh/bias)
// AMODE 0: A = half [M,K]
// AMODE 1: A[r,k] = relu(P[b*4+i,k] + Q[b*4+j,k]), r=(b,i,jj), j=jj+(jj>=i); K=512
// AMODE 2: A[r,k] = k<256 ? A[r,k] : A2[r,k-256]  (half [M,256] each); K=512
// EPI 0 none, 1 relu, 2 sigmoid.  OTYPE 0 half, 1 float.
// CTA: 256 threads (8 warps, 2x4), tile 128x256, K chunks of 64, double-buffered.

template<int AMODE>
__device__ __forceinline__ void stageA(uint32_t uAbuf, __half* smAbuf,
                                       const __half* __restrict__ A,
                                       const __half* __restrict__ A2,
                                       int row0, int kbase, int K, int tid)
{
    if (AMODE != 1) {
        #pragma unroll
        for (int p = 0; p < 4; ++p) {
            int lin = p * 256 + tid;
            int row = lin >> 3;
            int c8  = lin & 7;
            int gk  = kbase + c8 * 8;
            const __half* src;
            if (AMODE == 0) src = &A[(size_t)(row0 + row) * K + gk];
            else src = (gk < 256) ? &A [(size_t)(row0 + row) * 256 + gk]
                                  : &A2[(size_t)(row0 + row) * 256 + gk - 256];
            cp16(uAbuf + (uint32_t)(row * APADH + c8 * 8) * 2u, src);
        }
    } else {
        const __half2 z2 = __float2half2_rn(0.f);
        #pragma unroll
        for (int p = 0; p < 4; ++p) {
            int lin = p * 256 + tid;
            int row = lin >> 3;
            int c8  = lin & 7;
            int gr  = row0 + row;
            int b   = gr / 12;
            int rem = gr - b * 12;
            int i   = rem / 3;
            int jj  = rem - i * 3;
            int j   = jj + (jj >= i);
            int gk  = kbase + c8 * 8;
            const __half2* pp = reinterpret_cast<const __half2*>(&A [((size_t)b * 4 + i) * 512 + gk]);
            const __half2* qq = reinterpret_cast<const __half2*>(&A2[((size_t)b * 4 + j) * 512 + gk]);
            __half2 o[4];
            #pragma unroll
            for (int q = 0; q < 4; ++q)
                o[q] = __hmax2(__hadd2(pp[q], qq[q]), z2);
            *reinterpret_cast<uint4*>(&smAbuf[row * APADH + c8 * 8]) =
                *reinterpret_cast<uint4*>(o);
        }
    }
}

__device__ __forceinline__ void stageB(uint32_t uBbuf, const __half* __restrict__ Wh,
                                       int colblk, int kbase, int N, int tid)
{
    #pragma unroll
    for (int p = 0; p < 8; ++p) {
        int lin = p * 256 + tid;
        int k   = lin >> 5;          // 0..63
        int c8  = lin & 31;          // 32 chunks of 8 halves = 256 cols
        cp16(uBbuf + (uint32_t)(k * BPADH + c8 * 8) * 2u,
             &Wh[(size_t)(kbase + k) * N + colblk + c8 * 8]);
    }
}

template<int AMODE, int EPI, int OTYPE>
__global__ void __launch_bounds__(256)
gemm_h(const __half* __restrict__ A, const __half* __restrict__ A2,
       const __half* __restrict__ Wh, const float* __restrict__ bias,
       void* __restrict__ Cout, int K, int N)
{
    extern __shared__ __half sm[];
    __half* smA = sm;                              // [2][128][APADH]
    __half* smB = sm + 2 * 128 * APADH;            // [2][64][BPADH]
    const uint32_t uA = smem_u32(smA);
    const uint32_t uB = smem_u32(smB);

    const int tid    = threadIdx.x;
    const int lane   = tid & 31;
    const int warp   = tid >> 5;
    const int wm     = warp & 1;       // 2 in M
    const int wn     = warp >> 1;      // 4 in N
    const int row0   = blockIdx.y * 128;
    const int colblk = blockIdx.x * 256;

    float acc[4][8][4];
    #pragma unroll
    for (int a = 0; a < 4; ++a)
        #pragma unroll
        for (int b = 0; b < 8; ++b)
            #pragma unroll
            for (int q = 0; q < 4; ++q) acc[a][b][q] = 0.f;

    const int NC = K >> 6;
    stageA<AMODE>(uA, smA, A, A2, row0, 0, K, tid);
    stageB(uB, Wh, colblk, 0, N, tid);
    asm volatile("cp.async.commit_group;");

    // A ldmatrix.x4 lane addressing: group g=lane>>3:
    //   row = (g&1)*8 + (lane&7), col = (g>>1)*8
    const int aLrow = ((lane >> 3) & 1) * 8 + (lane & 7);
    const int aLcol = (lane >> 4) * 8;
    // B ldmatrix.x4.trans lane addressing
    const int lm   = lane >> 3;                 // 0..3
    const int lrow = (lane & 7) + (lm & 1) * 8; // k row 0..15
    const int lcol = (lm >> 1) * 8;             // n sub-offset 0 or 8

    for (int c = 0; c < NC; ++c) {
        const int b = c & 1;
        const uint32_t cA = uA + (uint32_t)(b * 128 * APADH) * 2u;
        const uint32_t cB = uB + (uint32_t)(b * 64 * BPADH) * 2u;
        if (c + 1 < NC) {
            stageA<AMODE>(uA + (uint32_t)((1 - b) * 128 * APADH) * 2u,
                          smA + (1 - b) * 128 * APADH,
                          A, A2, row0, (c + 1) * 64, K, tid);
            stageB(uB + (uint32_t)((1 - b) * 64 * BPADH) * 2u, Wh, colblk, (c + 1) * 64, N, tid);
            asm volatile("cp.async.commit_group;");
            asm volatile("cp.async.wait_group 1;");
        } else {
            asm volatile("cp.async.wait_group 0;");
        }
        __syncthreads();

        #pragma unroll
        for (int s = 0; s < 4; ++s) {           // 4 x k16 per 64-chunk
            const int kloc = s * 16;
            // B fragments: 4 x ldmatrix.x4.trans -> 8 n8 frags
            uint32_t bf[8][2];
            #pragma unroll
            for (int ntt = 0; ntt < 4; ++ntt) {
                uint32_t r[4];
                uint32_t addr = cB + (uint32_t)((kloc + lrow) * BPADH
                                 + wn * 64 + ntt * 16 + lcol) * 2u;
                ldmx4t(r, addr);
                bf[ntt * 2][0]     = r[0];
                bf[ntt * 2][1]     = r[1];
                bf[ntt * 2 + 1][0] = r[2];
                bf[ntt * 2 + 1][1] = r[3];
            }
            #pragma unroll
            for (int mt = 0; mt < 4; ++mt) {
                uint32_t af[4];
                uint32_t addr = cA + (uint32_t)((wm * 64 + mt * 16 + aLrow) * APADH
                                 + kloc + aLcol) * 2u;
                ldmx4(af, addr);
                #pragma unroll
                for (int nt = 0; nt < 8; ++nt)
                    mma16816(acc[mt][nt], af, bf[nt]);
            }
        }
        __syncthreads();
    }

    // ---- epilogue
    #pragma unroll
    for (int mt = 0; mt < 4; ++mt) {
        int r0 = row0 + wm * 64 + mt * 16 + (lane >> 2);
        #pragma unroll
        for (int nt = 0; nt < 8; ++nt) {
            int col = colblk + wn * 64 + nt * 8 + (lane & 3) * 2;
            float b0 = bias[col], b1 = bias[col + 1];
            float v0 = acc[mt][nt][0] + b0;
            float v1 = acc[mt][nt][1] + b1;
            float v2 = acc[mt][nt][2] + b0;
            float v3 = acc[mt][nt][3] + b1;
            if (EPI == 1) {
                v0 = fmaxf(v0, 0.f); v1 = fmaxf(v1, 0.f);
                v2 = fmaxf(v2, 0.f); v3 = fmaxf(v3, 0.f);
            } else if (EPI == 2) {
                v0 = 1.f / (1.f + __expf(-v0));
                v1 = 1.f / (1.f + __expf(-v1));
                v2 = 1.f / (1.f + __expf(-v2));
                v3 = 1.f / (1.f + __expf(-v3));
            }
            if (OTYPE == 0) {
                __half* C = (__half*)Cout;
                *reinterpret_cast<__half2*>(&C[(size_t)r0 * N + col])       = __floats2half2_rn(v0, v1);
                *reinterpret_cast<__half2*>(&C[(size_t)(r0 + 8) * N + col]) = __floats2half2_rn(v2, v3);
            } else {
                float* C = (float*)Cout;
                *reinterpret_cast<float2*>(&C[(size_t)r0 * N + col])       = make_float2(v0, v1);
                *reinterpret_cast<float2*>(&C[(size_t)(r0 + 8) * N + col]) = make_float2(v2, v3);
            }
        }
    }
}

// ---------------- launch ----------------
template<typename Tp>
static inline Tp* sym(const void* symbol)
{
    void* p = nullptr;
    cudaGetSymbolAddress(&p, symbol);
    return (Tp*)p;
}

#define SHM_BYTES ((2*128*APADH + 2*64*BPADH) * 2)

extern "C" void kernel_launch(void* const* d_in, const int* in_sizes, int n_in,
                              void* d_out, int out_size)
{
    const float* x   = (const float*)d_in[0];
    const float* ng0 = (const float*)d_in[1];
    const float* nb0 = (const float*)d_in[2];
    const float* nW0 = (const float*)d_in[3];
    const float* nc0 = (const float*)d_in[4];
    const float* ng1 = (const float*)d_in[5];
    const float* nb1 = (const float*)d_in[6];
    const float* nW1 = (const float*)d_in[7];
    const float* nc1 = (const float*)d_in[8];
    const float* mg0 = (const float*)d_in[9];
    const float* mb0 = (const float*)d_in[10];
    const float* mW0 = (const float*)d_in[11];
    const float* mc0 = (const float*)d_in[12];
    const float* mg1 = (const float*)d_in[13];
    const float* mb1 = (const float*)d_in[14];
    const float* mW1 = (const float*)d_in[15];
    const float* mc1 = (const float*)d_in[16];
    const float* fg0 = (const float*)d_in[17];
    const float* fb0 = (const float*)d_in[18];
    const float* fW0 = (const float*)d_in[19];
    const float* fc0 = (const float*)d_in[20];
    const float* fg1 = (const float*)d_in[21];
    const float* fb1 = (const float*)d_in[22];
    const float* fW1 = (const float*)d_in[23];
    const float* fc1 = (const float*)d_in[24];
    float* out = (float*)d_out;

    __half* xh    = sym<__half>(g_xh);
    __half* XNH   = sym<__half>(g_XNH);
    __half* XNODE = sym<__half>(g_XNODE);
    __half* P     = sym<__half>(g_P);
    __half* Q     = sym<__half>(g_Q);
    float*  XMSG  = sym<float >(g_XMSG);
    __half* XAGG  = sym<__half>(g_XAGG);
    __half* FH    = sym<__half>(g_FH);
    float*  part  = sym<float >(g_part);
    float*  mu    = sym<float >(g_mu);
    float*  var   = sym<float >(g_var);
    float*  S     = sym<float >(g_sbuf);
    float*  T     = sym<float >(g_tbuf);
    float*  zero  = sym<float >(g_zero);
    float*  BI    = sym<float >(g_bias);

    __half* Whn0 = sym<__half>(g_Whn0);
    __half* Whn1 = sym<__half>(g_Whn1);
    __half* Whp  = sym<__half>(g_Whp);
    __half* Whq  = sym<__half>(g_Whq);
    __half* Whm1 = sym<__half>(g_Whm1);
    __half* Whf0 = sym<__half>(g_Whf0);
    __half* Whf1 = sym<__half>(g_Whf1);

    float *s_n0 = S + 0*512, *t_n0 = T + 0*512, *b_n0 = BI + 0*512;
    float *s_n1 = S + 1*512, *t_n1 = T + 1*512, *b_n1 = BI + 1*512;
    float *s_p  = S + 2*512, *t_p  = T + 2*512, *b_p  = BI + 2*512;
    float *s_q  = S + 3*512, *t_q  = T + 3*512, *b_q  = BI + 3*512;
    float *s_m1 = S + 4*512, *t_m1 = T + 4*512, *b_m1 = BI + 4*512;
    float *s_f0 = S + 5*512, *t_f0 = T + 5*512, *b_f0 = BI + 5*512;
    float *s_f1 = S + 6*512, *t_f1 = T + 6*512, *b_f1 = BI + 6*512;

    cudaFuncSetAttribute(gemm_h<0,1,0>, cudaFuncAttributeMaxDynamicSharedMemorySize, SHM_BYTES);
    cudaFuncSetAttribute(gemm_h<0,2,0>, cudaFuncAttributeMaxDynamicSharedMemorySize, SHM_BYTES);
    cudaFuncSetAttribute(gemm_h<0,0,0>, cudaFuncAttributeMaxDynamicSharedMemorySize, SHM_BYTES);
    cudaFuncSetAttribute(gemm_h<1,2,1>, cudaFuncAttributeMaxDynamicSharedMemorySize, SHM_BYTES);
    cudaFuncSetAttribute(gemm_h<2,1,0>, cudaFuncAttributeMaxDynamicSharedMemorySize, SHM_BYTES);
    cudaFuncSetAttribute(gemm_h<0,2,1>, cudaFuncAttributeMaxDynamicSharedMemorySize, SHM_BYTES);

    // ---- input convert + stats
    cvt_x<<<(size_t)M4 * 256 / (256 * 4), 256>>>(x, xh);
    colstats_partial_f<<<NCHUNK, 256>>>(x, M4, 256, part);
    colstats_final    <<<1, 256>>>(part, 256, M4, mu, var);
    fold_bn<<<1, 256>>>(ng0,       nb0,       mu, var, s_n0, t_n0);
    fold_bn<<<1, 256>>>(mg0,       mb0,       mu, var, s_p,  t_p);
    fold_bn<<<1, 256>>>(mg0 + 256, mb0 + 256, mu, var, s_q,  t_q);
    fold_w   <<<256*512/256, 256>>>(nW0,             s_n0, Whn0, 512);
    fold_bias<<<4, 128>>>(nW0,             t_n0, nc0,  b_n0, 256, 512);
    fold_w   <<<256*512/256, 256>>>(mW0,             s_p,  Whp,  512);
    fold_bias<<<4, 128>>>(mW0,             t_p,  zero, b_p,  256, 512);
    fold_w   <<<256*512/256, 256>>>(mW0 + 256 * 512, s_q,  Whq,  512);
    fold_bias<<<4, 128>>>(mW0 + 256 * 512, t_q,  mc0,  b_q,  256, 512);

    // ---- node MLP
    gemm_h<0,1,0><<<dim3(2, M4/128), 256, SHM_BYTES>>>(xh, nullptr, Whn0, b_n0, XNH, 256, 512);
    colstats_partial_h<<<NCHUNK, 512>>>(XNH, M4, 512, part);
    colstats_final    <<<1, 512>>>(part, 512, M4, mu, var);
    fold_bn<<<1, 512>>>(ng1, nb1, mu, var, s_n1, t_n1);
    fold_w   <<<512*256/256, 256>>>(nW1, s_n1, Whn1, 256);
    fold_bias<<<2, 128>>>(nW1, t_n1, nc1, b_n1, 512, 256);
    gemm_h<0,2,0><<<dim3(1, M4/128), 256, SHM_BYTES>>>(XNH, nullptr, Whn1, b_n1, XNODE, 512, 256);

    // ---- msg MLP layer-0 via P/Q factorization
    gemm_h<0,0,0><<<dim3(2, M4/128), 256, SHM_BYTES>>>(xh, nullptr, Whp, b_p, P, 256, 512);
    gemm_h<0,0,0><<<dim3(2, M4/128), 256, SHM_BYTES>>>(xh, nullptr, Whq, b_q, Q, 256, 512);

    // ---- msg hidden stats (HM never materialized)
    pqstats_partial<<<NCHUNK, 512>>>(P, Q, part);
    colstats_final <<<1, 512>>>(part, 512, M12, mu, var);
    fold_bn<<<1, 512>>>(mg1, mb1, mu, var, s_m1, t_m1);
    fold_w   <<<512*256/256, 256>>>(mW1, s_m1, Whm1, 256);
    fold_bias<<<2, 128>>>(mW1, t_m1, mc1, b_m1, 512, 256);

    // ---- msg MLP layer-1, A = relu(P+Q) on the fly
    gemm_h<1,2,1><<<dim3(1, M12/128), 256, SHM_BYTES>>>(P, Q, Whm1, b_m1, XMSG, 512, 256);
    avg3<<<(size_t)M4 * 64 / 256, 256>>>(XMSG, XAGG);

    // ---- final MLP, A = concat(XNODE, XAGG) on the fly
    colstats_partial_h<<<NCHUNK, 256>>>(XNODE, M4, 256, part);
    colstats_final    <<<1, 256>>>(part, 256, M4, mu, var);
    colstats_partial_h<<<NCHUNK, 256>>>(XAGG, M4, 256, part);
    colstats_final    <<<1, 256>>>(part, 256, M4, mu + 256, var + 256);
    fold_bn<<<1, 512>>>(fg0, fb0, mu, var, s_f0, t_f0);
    fold_w   <<<512*512/256, 256>>>(fW0, s_f0, Whf0, 512);
    fold_bias<<<4, 128>>>(fW0, t_f0, fc0, b_f0, 512, 512);
    gemm_h<2,1,0><<<dim3(2, M4/128), 256, SHM_BYTES>>>(XNODE, XAGG, Whf0, b_f0, FH, 512, 512);
    colstats_partial_h<<<NCHUNK, 512>>>(FH, M4, 512, part);
    colstats_final    <<<1, 512>>>(part, 512, M4, mu, var);
    fold_bn<<<1, 512>>>(fg1, fb1, mu, var, s_f1, t_f1);
    fold_w   <<<512*256/256, 256>>>(fW1, s_f1, Whf1, 256);
    fold_bias<<<2, 128>>>(fW1, t_f1, fc1, b_f1, 512, 256);
    gemm_h<0,2,1><<<dim3(1, M4/128), 256, SHM_BYTES>>>(FH, nullptr, Whf1, b_f1, out, 512, 256);
}

// round 6
// speedup vs baseline: 3.1903x; 1.0665x over previous
#include <cuda_runtime.h>
#include <cuda_fp16.h>
#include <cstdint>
#include <math.h>

// ---------------- problem constants ----------------
#define BATCH   16384
#define M4      65536
#define M12     196608
#define EPS     1e-5f
#define NCHUNK  256

#define APADH 40    // A smem row stride in halves (32-k tile + 8)   -> 80B
#define BPADH 264   // B smem row stride in halves (256-n tile + 8)  -> 528B

// ---------------- PTX helpers (plain sm_80+ PTX only) ----------------
__device__ __forceinline__ void cp16(uint32_t dst, const void* src) {
    asm volatile("cp.async.cg.shared.global [%0], [%1], 16;" :: "r"(dst), "l"(src));
}
__device__ __forceinline__ uint32_t smem_u32(const void* p) {
    uint32_t a;
    asm("{ .reg .u64 t; cvta.to.shared.u64 t, %1; cvt.u32.u64 %0, t; }" : "=r"(a) : "l"(p));
    return a;
}
__device__ __forceinline__ void mma16816(float* c, const uint32_t* a, const uint32_t* b) {
    asm volatile(
        "mma.sync.aligned.m16n8k16.row.col.f32.f16.f16.f32 "
        "{%0,%1,%2,%3},{%4,%5,%6,%7},{%8,%9},{%0,%1,%2,%3};"
        : "+f"(c[0]), "+f"(c[1]), "+f"(c[2]), "+f"(c[3])
        : "r"(a[0]), "r"(a[1]), "r"(a[2]), "r"(a[3]), "r"(b[0]), "r"(b[1]));
}
__device__ __forceinline__ void ldmx4(uint32_t* r, uint32_t addr) {
    asm volatile("ldmatrix.sync.aligned.m8n8.x4.shared.b16 {%0,%1,%2,%3}, [%4];"
        : "=r"(r[0]), "=r"(r[1]), "=r"(r[2]), "=r"(r[3]) : "r"(addr));
}
__device__ __forceinline__ void ldmx4t(uint32_t* r, uint32_t addr) {
    asm volatile("ldmatrix.sync.aligned.m8n8.x4.trans.shared.b16 {%0,%1,%2,%3}, [%4];"
        : "=r"(r[0]), "=r"(r[1]), "=r"(r[2]), "=r"(r[3]) : "r"(addr));
}

// ---------------- static scratch ----------------
__device__ __half g_xh    [(size_t)M4  * 256];
__device__ __half g_XNH   [(size_t)M4  * 512];
__device__ __half g_XNODE [(size_t)M4  * 256];
__device__ __half g_P     [(size_t)M4  * 512];
__device__ __half g_Q     [(size_t)M4  * 512];
__device__ __half g_XMSG  [(size_t)M12 * 256];
__device__ __half g_XAGG  [(size_t)M4  * 256];
__device__ __half g_FH    [(size_t)M4  * 512];

__device__ float  g_part  [2 * NCHUNK * 512];
__device__ float  g_sbuf  [7 * 512];
__device__ float  g_tbuf  [7 * 512];
__device__ float  g_zero  [512];
__device__ float  g_bias  [7 * 512];

// folded half weights
__device__ __half g_Whn0 [256 * 512];
__device__ __half g_Whn1 [512 * 256];
__device__ __half g_Whp  [256 * 512];
__device__ __half g_Whq  [256 * 512];
__device__ __half g_Whm1 [512 * 256];
__device__ __half g_Whf0 [512 * 512];
__device__ __half g_Whf1 [512 * 256];

// ---------------- small kernels ----------------
__global__ void cvt_x(const float* __restrict__ x, __half* __restrict__ xh)
{
    size_t i = ((size_t)blockIdx.x * blockDim.x + threadIdx.x) * 4;
    float4 v = *reinterpret_cast<const float4*>(&x[i]);
    *reinterpret_cast<__half2*>(&xh[i])     = __floats2half2_rn(v.x, v.y);
    *reinterpret_cast<__half2*>(&xh[i + 2]) = __floats2half2_rn(v.z, v.w);
}

__global__ void colstats_partial_h(const __half* __restrict__ A, int M, int C,
                                   float* __restrict__ part)
{
    int c = threadIdx.x;
    float sm = 0.f, ss = 0.f;
    for (int r = blockIdx.x; r < M; r += gridDim.x) {
        float v = __half2float(A[(size_t)r * C + c]);
        sm += v; ss += v * v;
    }
    part[(size_t)blockIdx.x * C + c]            = sm;
    part[(size_t)(NCHUNK + blockIdx.x) * C + c] = ss;
}

// final reduce + fold up to 3 BN affine sets into (s,t)
__global__ void colstats_final_fold(const float* __restrict__ part, int C, int M,
    const float* g0, const float* b0, float* s0, float* t0,
    const float* g1, const float* b1, float* s1, float* t1,
    const float* g2, const float* b2, float* s2, float* t2)
{
    int c = threadIdx.x;
    float sm = 0.f, ss = 0.f;
    for (int i = 0; i < NCHUNK; ++i) {
        sm += part[(size_t)i * C + c];
        ss += part[(size_t)(NCHUNK + i) * C + c];
    }
    float m = sm / (float)M;
    float v = ss / (float)M - m * m;
    float r = rsqrtf(v + EPS);
    { float sc = g0[c] * r; s0[c] = sc; t0[c] = b0[c] - m * sc; }
    if (g1) { float sc = g1[c] * r; s1[c] = sc; t1[c] = b1[c] - m * sc; }
    if (g2) { float sc = g2[c] * r; s2[c] = sc; t2[c] = b2[c] - m * sc; }
}

__global__ void pqstats_partial(const __half* __restrict__ P, const __half* __restrict__ Q,
                                float* __restrict__ part)
{
    int c = threadIdx.x;  // 512
    float sm = 0.f, ss = 0.f;
    for (int b = blockIdx.x; b < BATCH; b += gridDim.x) {
        float pv[4], qv[4];
        #pragma unroll
        for (int i = 0; i < 4; ++i) {
            pv[i] = __half2float(P[((size_t)b * 4 + i) * 512 + c]);
            qv[i] = __half2float(Q[((size_t)b * 4 + i) * 512 + c]);
        }
        #pragma unroll
        for (int i = 0; i < 4; ++i)
            #pragma unroll
            for (int j = 0; j < 4; ++j)
                if (i != j) {
                    float v = fmaxf(pv[i] + qv[j], 0.f);
                    sm += v; ss += v * v;
                }
    }
    part[(size_t)blockIdx.x * 512 + c]            = sm;
    part[(size_t)(NCHUNK + blockIdx.x) * 512 + c] = ss;
}

// Wh[k][n] = half(W[k][n] * s[k])
__global__ void fold_w(const float* __restrict__ W, const float* __restrict__ s,
                       __half* __restrict__ Wh, int N)
{
    int idx = blockIdx.x * blockDim.x + threadIdx.x;
    int k = idx / N;
    Wh[idx] = __float2half(W[idx] * s[k]);
}

// bout[n] = c[n] + sum_k t[k]*W[k][n]
__global__ void fold_bias(const float* __restrict__ W, const float* __restrict__ t,
                          const float* __restrict__ c, float* __restrict__ bout,
                          int K, int N)
{
    int n = blockIdx.x * blockDim.x + threadIdx.x;
    if (n >= N) return;
    float a = c[n];
    for (int k = 0; k < K; ++k) a += t[k] * W[(size_t)k * N + n];
    bout[n] = a;
}

__global__ void avg3(const __half* __restrict__ XMSG, __half* __restrict__ XAGG)
{
    size_t idx = (size_t)blockIdx.x * blockDim.x + threadIdx.x; // M4*64 quads
    int    c4  = (int)(idx & 63);
    size_t bi  = idx >> 6;
    const __half2* m = reinterpret_cast<const __half2*>(XMSG);
    size_t base = (bi * 3) * 128 + c4 * 2;
    __half2 a0 = m[base],       a1 = m[base + 1];
    __half2 b0 = m[base + 128], b1 = m[base + 129];
    __half2 c0 = m[base + 256], c1 = m[base + 257];
    const float inv3 = 1.f / 3.f;
    float2 fa0 = __half22float2(a0), fb0 = __half22float2(b0), fc0 = __half22float2(c0);
    float2 fa1 = __half22float2(a1), fb1 = __half22float2(b1), fc1 = __half22float2(c1);
    __half2 o0 = __floats2half2_rn((fa0.x + fb0.x + fc0.x) * inv3, (fa0.y + fb0.y + fc0.y) * inv3);
    __half2 o1 = __floats2half2_rn((fa1.x + fb1.x + fc1.x) * inv3, (fa1.y + fb1.y + fc1.y) * inv3);
    *reinterpret_cast<__half2*>(&XAGG[bi * 256 + c4 * 4])     = o0;
    *reinterpret_cast<__half2*>(&XAGG[bi * 256 + c4 * 4 + 2]) = o1;
}

// ---------------- fp16 mma GEMM -----------------------------------------------
// C[M,N] = epi( A[M,K] @ Wh[K,N] + bias )    (BN folded into Wh/bias)
// AMODE 0: A = half [M,K]
// AMODE 1: A[r,k] = relu(P[b*4+i,k] + Q[b*4+j,k]), r=(b,i,jj), j=jj+(jj>=i); K=512
// AMODE 2: A[r,k] = k<256 ? A[r,k] : A2[r,k-256]  (half [M,256] each); K=512
// EPI 0 none, 1 relu, 2 sigmoid.  OTYPE 0 half, 1 float.
// CTA: 128 threads (4 warps, 1x4), tile 64x256, k32 chunks, 4-stage cp.async pipe.

#define NSTAGE 4
#define A_ST  (64 * APADH)          // halves per A stage
#define B_ST  (32 * BPADH)          // halves per B stage
#define SHM_BYTES ((NSTAGE * (A_ST + B_ST)) * 2)

template<int AMODE>
__device__ __forceinline__ void stageA(uint32_t uAbuf, __half* smAbuf,
                                       const __half* __restrict__ A,
                                       const __half* __restrict__ A2,
                                       int row0, int kbase, int K, int tid)
{
    if (AMODE != 1) {
        #pragma unroll
        for (int p = 0; p < 2; ++p) {
            int lin = p * 128 + tid;
            int row = lin >> 2;
            int c8  = lin & 3;
            int gk  = kbase + c8 * 8;
            const __half* src;
            if (AMODE == 0) src = &A[(size_t)(row0 + row) * K + gk];
            else src = (gk < 256) ? &A [(size_t)(row0 + row) * 256 + gk]
                                  : &A2[(size_t)(row0 + row) * 256 + gk - 256];
            cp16(uAbuf + (uint32_t)(row * APADH + c8 * 8) * 2u, src);
        }
    } else {
        const __half2 z2 = __float2half2_rn(0.f);
        #pragma unroll
        for (int p = 0; p < 2; ++p) {
            int lin = p * 128 + tid;
            int row = lin >> 2;
            int c8  = lin & 3;
            int gr  = row0 + row;
            int b   = gr / 12;
            int rem = gr - b * 12;
            int i   = rem / 3;
            int jj  = rem - i * 3;
            int j   = jj + (jj >= i);
            int gk  = kbase + c8 * 8;
            uint4 pv4 = *reinterpret_cast<const uint4*>(&A [((size_t)b * 4 + i) * 512 + gk]);
            uint4 qv4 = *reinterpret_cast<const uint4*>(&A2[((size_t)b * 4 + j) * 512 + gk]);
            const __half2* ph = reinterpret_cast<const __half2*>(&pv4);
            const __half2* qh = reinterpret_cast<const __half2*>(&qv4);
            __half2 o[4];
            #pragma unroll
            for (int q = 0; q < 4; ++q)
                o[q] = __hmax2(__hadd2(ph[q], qh[q]), z2);
            *reinterpret_cast<uint4*>(&smAbuf[row * APADH + c8 * 8]) =
                *reinterpret_cast<uint4*>(o);
        }
    }
}

__device__ __forceinline__ void stageB(uint32_t uBbuf, const __half* __restrict__ Wh,
                                       int colblk, int kbase, int N, int tid)
{
    #pragma unroll
    for (int p = 0; p < 8; ++p) {
        int lin = p * 128 + tid;
        int k   = lin >> 5;          // 0..31
        int c8  = lin & 31;          // 32 chunks of 8 halves = 256 cols
        cp16(uBbuf + (uint32_t)(k * BPADH + c8 * 8) * 2u,
             &Wh[(size_t)(kbase + k) * N + colblk + c8 * 8]);
    }
}

template<int AMODE, int EPI, int OTYPE>
__global__ void __launch_bounds__(128, 2)
gemm_h(const __half* __restrict__ A, const __half* __restrict__ A2,
       const __half* __restrict__ Wh, const float* __restrict__ bias,
       void* __restrict__ Cout, int K, int N)
{
    extern __shared__ __half sm[];
    __half* smA = sm;                              // [NSTAGE][64][APADH]
    __half* smB = sm + NSTAGE * A_ST;              // [NSTAGE][32][BPADH]
    const uint32_t uA = smem_u32(smA);
    const uint32_t uB = smem_u32(smB);

    const int tid    = threadIdx.x;
    const int lane   = tid & 31;
    const int wn     = tid >> 5;       // 4 warps in N
    const int row0   = blockIdx.y * 64;
    const int colblk = blockIdx.x * 256;

    float acc[4][8][4];
    #pragma unroll
    for (int a = 0; a < 4; ++a)
        #pragma unroll
        for (int b = 0; b < 8; ++b)
            #pragma unroll
            for (int q = 0; q < 4; ++q) acc[a][b][q] = 0.f;

    const int NC = K >> 5;
    // prologue: stages 0..2
    #pragma unroll
    for (int s = 0; s < 3; ++s) {
        stageA<AMODE>(uA + (uint32_t)(s * A_ST) * 2u, smA + s * A_ST, A, A2, row0, s * 32, K, tid);
        stageB(uB + (uint32_t)(s * B_ST) * 2u, Wh, colblk, s * 32, N, tid);
        asm volatile("cp.async.commit_group;");
    }

    // lane addressing
    const int aLrow = ((lane >> 3) & 1) * 8 + (lane & 7);
    const int aLcol = (lane >> 4) * 8;
    const int lm    = lane >> 3;
    const int lrow  = (lane & 7) + (lm & 1) * 8;
    const int lcol  = (lm >> 1) * 8;

    for (int c = 0; c < NC; ++c) {
        asm volatile("cp.async.wait_group 2;");
        __syncthreads();
        // issue stage c+3 (empty commit in tail keeps group count uniform)
        if (c + 3 < NC) {
            int s = (c + 3) & (NSTAGE - 1);
            stageA<AMODE>(uA + (uint32_t)(s * A_ST) * 2u, smA + s * A_ST, A, A2, row0, (c + 3) * 32, K, tid);
            stageB(uB + (uint32_t)(s * B_ST) * 2u, Wh, colblk, (c + 3) * 32, N, tid);
        }
        asm volatile("cp.async.commit_group;");

        const int sb = c & (NSTAGE - 1);
        const uint32_t cA = uA + (uint32_t)(sb * A_ST) * 2u;
        const uint32_t cB = uB + (uint32_t)(sb * B_ST) * 2u;

        #pragma unroll
        for (int s = 0; s < 2; ++s) {           // 2 x k16 per 32-chunk
            const int kloc = s * 16;
            uint32_t bf[8][2];
            #pragma unroll
            for (int ntt = 0; ntt < 4; ++ntt) {
                uint32_t r[4];
                uint32_t addr = cB + (uint32_t)((kloc + lrow) * BPADH
                                 + wn * 64 + ntt * 16 + lcol) * 2u;
                ldmx4t(r, addr);
                bf[ntt * 2][0]     = r[0];
                bf[ntt * 2][1]     = r[1];
                bf[ntt * 2 + 1][0] = r[2];
                bf[ntt * 2 + 1][1] = r[3];
            }
            #pragma unroll
            for (int mt = 0; mt < 4; ++mt) {
                uint32_t af[4];
                uint32_t addr = cA + (uint32_t)((mt * 16 + aLrow) * APADH + kloc + aLcol) * 2u;
                ldmx4(af, addr);
                #pragma unroll
                for (int nt = 0; nt < 8; ++nt)
                    mma16816(acc[mt][nt], af, bf[nt]);
            }
        }
    }

    // ---- epilogue
    #pragma unroll
    for (int mt = 0; mt < 4; ++mt) {
        int r0 = row0 + mt * 16 + (lane >> 2);
        #pragma unroll
        for (int nt = 0; nt < 8; ++nt) {
            int col = colblk + wn * 64 + nt * 8 + (lane & 3) * 2;
            float b0 = bias[col], b1 = bias[col + 1];
            float v0 = acc[mt][nt][0] + b0;
            float v1 = acc[mt][nt][1] + b1;
            float v2 = acc[mt][nt][2] + b0;
            float v3 = acc[mt][nt][3] + b1;
            if (EPI == 1) {
                v0 = fmaxf(v0, 0.f); v1 = fmaxf(v1, 0.f);
                v2 = fmaxf(v2, 0.f); v3 = fmaxf(v3, 0.f);
            } else if (EPI == 2) {
                v0 = 1.f / (1.f + __expf(-v0));
                v1 = 1.f / (1.f + __expf(-v1));
                v2 = 1.f / (1.f + __expf(-v2));
                v3 = 1.f / (1.f + __expf(-v3));
            }
            if (OTYPE == 0) {
                __half* C = (__half*)Cout;
                *reinterpret_cast<__half2*>(&C[(size_t)r0 * N + col])       = __floats2half2_rn(v0, v1);
                *reinterpret_cast<__half2*>(&C[(size_t)(r0 + 8) * N + col]) = __floats2half2_rn(v2, v3);
            } else {
                float* C = (float*)Cout;
                *reinterpret_cast<float2*>(&C[(size_t)r0 * N + col])       = make_float2(v0, v1);
                *reinterpret_cast<float2*>(&C[(size_t)(r0 + 8) * N + col]) = make_float2(v2, v3);
            }
        }
    }
}

// ---------------- launch ----------------
template<typename Tp>
static inline Tp* sym(const void* symbol)
{
    void* p = nullptr;
    cudaGetSymbolAddress(&p, symbol);
    return (Tp*)p;
}

extern "C" void kernel_launch(void* const* d_in, const int* in_sizes, int n_in,
                              void* d_out, int out_size)
{
    const float* x   = (const float*)d_in[0];
    const float* ng0 = (const float*)d_in[1];
    const float* nb0 = (const float*)d_in[2];
    const float* nW0 = (const float*)d_in[3];
    const float* nc0 = (const float*)d_in[4];
    const float* ng1 = (const float*)d_in[5];
    const float* nb1 = (const float*)d_in[6];
    const float* nW1 = (const float*)d_in[7];
    const float* nc1 = (const float*)d_in[8];
    const float* mg0 = (const float*)d_in[9];
    const float* mb0 = (const float*)d_in[10];
    const float* mW0 = (const float*)d_in[11];
    const float* mc0 = (const float*)d_in[12];
    const float* mg1 = (const float*)d_in[13];
    const float* mb1 = (const float*)d_in[14];
    const float* mW1 = (const float*)d_in[15];
    const float* mc1 = (const float*)d_in[16];
    const float* fg0 = (const float*)d_in[17];
    const float* fb0 = (const float*)d_in[18];
    const float* fW0 = (const float*)d_in[19];
    const float* fc0 = (const float*)d_in[20];
    const float* fg1 = (const float*)d_in[21];
    const float* fb1 = (const float*)d_in[22];
    const float* fW1 = (const float*)d_in[23];
    const float* fc1 = (const float*)d_in[24];
    float* out = (float*)d_out;

    __half* xh    = sym<__half>(g_xh);
    __half* XNH   = sym<__half>(g_XNH);
    __half* XNODE = sym<__half>(g_XNODE);
    __half* P     = sym<__half>(g_P);
    __half* Q     = sym<__half>(g_Q);
    __half* XMSG  = sym<__half>(g_XMSG);
    __half* XAGG  = sym<__half>(g_XAGG);
    __half* FH    = sym<__half>(g_FH);
    float*  part  = sym<float >(g_part);
    float*  S     = sym<float >(g_sbuf);
    float*  T     = sym<float >(g_tbuf);
    float*  zero  = sym<float >(g_zero);
    float*  BI    = sym<float >(g_bias);

    __half* Whn0 = sym<__half>(g_Whn0);
    __half* Whn1 = sym<__half>(g_Whn1);
    __half* Whp  = sym<__half>(g_Whp);
    __half* Whq  = sym<__half>(g_Whq);
    __half* Whm1 = sym<__half>(g_Whm1);
    __half* Whf0 = sym<__half>(g_Whf0);
    __half* Whf1 = sym<__half>(g_Whf1);

    float *s_n0 = S + 0*512, *t_n0 = T + 0*512, *b_n0 = BI + 0*512;
    float *s_n1 = S + 1*512, *t_n1 = T + 1*512, *b_n1 = BI + 1*512;
    float *s_p  = S + 2*512, *t_p  = T + 2*512, *b_p  = BI + 2*512;
    float *s_q  = S + 3*512, *t_q  = T + 3*512, *b_q  = BI + 3*512;
    float *s_m1 = S + 4*512, *t_m1 = T + 4*512, *b_m1 = BI + 4*512;
    float *s_f0 = S + 5*512, *t_f0 = T + 5*512, *b_f0 = BI + 5*512;
    float *s_f1 = S + 6*512, *t_f1 = T + 6*512, *b_f1 = BI + 6*512;

    cudaFuncSetAttribute(gemm_h<0,1,0>, cudaFuncAttributeMaxDynamicSharedMemorySize, SHM_BYTES);
    cudaFuncSetAttribute(gemm_h<0,2,0>, cudaFuncAttributeMaxDynamicSharedMemorySize, SHM_BYTES);
    cudaFuncSetAttribute(gemm_h<0,0,0>, cudaFuncAttributeMaxDynamicSharedMemorySize, SHM_BYTES);
    cudaFuncSetAttribute(gemm_h<1,2,0>, cudaFuncAttributeMaxDynamicSharedMemorySize, SHM_BYTES);
    cudaFuncSetAttribute(gemm_h<2,1,0>, cudaFuncAttributeMaxDynamicSharedMemorySize, SHM_BYTES);
    cudaFuncSetAttribute(gemm_h<0,2,1>, cudaFuncAttributeMaxDynamicSharedMemorySize, SHM_BYTES);

    // ---- input convert + stats (stats from half x: matches what GEMM consumes)
    cvt_x<<<(size_t)M4 * 256 / (256 * 4), 256>>>(x, xh);
    colstats_partial_h<<<NCHUNK, 256>>>(xh, M4, 256, part);
    colstats_final_fold<<<1, 256>>>(part, 256, M4,
        ng0, nb0, s_n0, t_n0,
        mg0, mb0, s_p,  t_p,
        mg0 + 256, mb0 + 256, s_q, t_q);
    fold_w   <<<256*512/256, 256>>>(nW0,             s_n0, Whn0, 512);
    fold_bias<<<4, 128>>>(nW0,             t_n0, nc0,  b_n0, 256, 512);
    fold_w   <<<256*512/256, 256>>>(mW0,             s_p,  Whp,  512);
    fold_bias<<<4, 128>>>(mW0,             t_p,  zero, b_p,  256, 512);
    fold_w   <<<256*512/256, 256>>>(mW0 + 256 * 512, s_q,  Whq,  512);
    fold_bias<<<4, 128>>>(mW0 + 256 * 512, t_q,  mc0,  b_q,  256, 512);

    // ---- node MLP
    gemm_h<0,1,0><<<dim3(2, M4/64), 128, SHM_BYTES>>>(xh, nullptr, Whn0, b_n0, XNH, 256, 512);
    colstats_partial_h<<<NCHUNK, 512>>>(XNH, M4, 512, part);
    colstats_final_fold<<<1, 512>>>(part, 512, M4,
        ng1, nb1, s_n1, t_n1, nullptr,nullptr,nullptr,nullptr, nullptr,nullptr,nullptr,nullptr);
    fold_w   <<<512*256/256, 256>>>(nW1, s_n1, Whn1, 256);
    fold_bias<<<2, 128>>>(nW1, t_n1, nc1, b_n1, 512, 256);
    gemm_h<0,2,0><<<dim3(1, M4/64), 128, SHM_BYTES>>>(XNH, nullptr, Whn1, b_n1, XNODE, 512, 256);

    // ---- msg MLP layer-0 via P/Q factorization
    gemm_h<0,0,0><<<dim3(2, M4/64), 128, SHM_BYTES>>>(xh, nullptr, Whp, b_p, P, 256, 512);
    gemm_h<0,0,0><<<dim3(2, M4/64), 128, SHM_BYTES>>>(xh, nullptr, Whq, b_q, Q, 256, 512);

    // ---- msg hidden stats (HM never materialized)
    pqstats_partial<<<NCHUNK, 512>>>(P, Q, part);
    colstats_final_fold<<<1, 512>>>(part, 512, M12,
        mg1, mb1, s_m1, t_m1, nullptr,nullptr,nullptr,nullptr, nullptr,nullptr,nullptr,nullptr);
    fold_w   <<<512*256/256, 256>>>(mW1, s_m1, Whm1, 256);
    fold_bias<<<2, 128>>>(mW1, t_m1, mc1, b_m1, 512, 256);

    // ---- msg MLP layer-1, A = relu(P+Q) on the fly
    gemm_h<1,2,0><<<dim3(1, M12/64), 128, SHM_BYTES>>>(P, Q, Whm1, b_m1, XMSG, 512, 256);
    avg3<<<(size_t)M4 * 64 / 256, 256>>>(XMSG, XAGG);

    // ---- final MLP, A = concat(XNODE, XAGG) on the fly
    colstats_partial_h<<<NCHUNK, 256>>>(XNODE, M4, 256, part);
    colstats_final_fold<<<1, 256>>>(part, 256, M4,
        fg0, fb0, s_f0, t_f0, nullptr,nullptr,nullptr,nullptr, nullptr,nullptr,nullptr,nullptr);
    colstats_partial_h<<<NCHUNK, 256>>>(XAGG, M4, 256, part);
    colstats_final_fold<<<1, 256>>>(part, 256, M4,
        fg0 + 256, fb0 + 256, s_f0 + 256, t_f0 + 256,
        nullptr,nullptr,nullptr,nullptr, nullptr,nullptr,nullptr,nullptr);
    fold_w   <<<512*512/256, 256>>>(fW0, s_f0, Whf0, 512);
    fold_bias<<<4, 128>>>(fW0, t_f0, fc0, b_f0, 512, 512);
    gemm_h<2,1,0><<<dim3(2, M4/64), 128, SHM_BYTES>>>(XNODE, XAGG, Whf0, b_f0, FH, 512, 512);
    colstats_partial_h<<<NCHUNK, 512>>>(FH, M4, 512, part);
    colstats_final_fold<<<1, 512>>>(part, 512, M4,
        fg1, fb1, s_f1, t_f1, nullptr,nullptr,nullptr,nullptr, nullptr,nullptr,nullptr,nullptr);
    fold_w   <<<512*256/256, 256>>>(fW1, s_f1, Whf1, 256);
    fold_bias<<<2, 128>>>(fW1, t_f1, fc1, b_f1, 512, 256);
    gemm_h<0,2,1><<<dim3(1, M4/64), 128, SHM_BYTES>>>(FH, nullptr, Whf1, b_f1, out, 512, 256);
}

// round 7
// speedup vs baseline: 3.8617x; 1.2104x over previous
#include <cuda_runtime.h>
#include <cuda_fp16.h>
#include <cstdint>
#include <math.h>

// ---------------- problem constants ----------------
#define BATCH   16384
#define M4      65536
#define M12     196608
#define EPS     1e-5f
#define NCHUNK  256
#define GY4     (M4 / 64)       // 1024 CTA rows for M4 GEMMs

#define APADH 40    // A smem row stride in halves
#define BPADH 264   // B smem row stride in halves

// ---------------- PTX helpers (plain sm_80+ PTX only) ----------------
__device__ __forceinline__ void cp16(uint32_t dst, const void* src) {
    asm volatile("cp.async.cg.shared.global [%0], [%1], 16;" :: "r"(dst), "l"(src));
}
__device__ __forceinline__ uint32_t smem_u32(const void* p) {
    uint32_t a;
    asm("{ .reg .u64 t; cvta.to.shared.u64 t, %1; cvt.u32.u64 %0, t; }" : "=r"(a) : "l"(p));
    return a;
}
__device__ __forceinline__ void mma16816(float* c, const uint32_t* a, const uint32_t* b) {
    asm volatile(
        "mma.sync.aligned.m16n8k16.row.col.f32.f16.f16.f32 "
        "{%0,%1,%2,%3},{%4,%5,%6,%7},{%8,%9},{%0,%1,%2,%3};"
        : "+f"(c[0]), "+f"(c[1]), "+f"(c[2]), "+f"(c[3])
        : "r"(a[0]), "r"(a[1]), "r"(a[2]), "r"(a[3]), "r"(b[0]), "r"(b[1]));
}
__device__ __forceinline__ void ldmx4(uint32_t* r, uint32_t addr) {
    asm volatile("ldmatrix.sync.aligned.m8n8.x4.shared.b16 {%0,%1,%2,%3}, [%4];"
        : "=r"(r[0]), "=r"(r[1]), "=r"(r[2]), "=r"(r[3]) : "r"(addr));
}
__device__ __forceinline__ void ldmx4t(uint32_t* r, uint32_t addr) {
    asm volatile("ldmatrix.sync.aligned.m8n8.x4.trans.shared.b16 {%0,%1,%2,%3}, [%4];"
        : "=r"(r[0]), "=r"(r[1]), "=r"(r[2]), "=r"(r[3]) : "r"(addr));
}

// ---------------- static scratch ----------------
__device__ __half g_xh    [(size_t)M4  * 256];
__device__ __half g_XNH   [(size_t)M4  * 512];
__device__ __half g_XNODE [(size_t)M4  * 256];
__device__ __half g_P     [(size_t)M4  * 512];
__device__ __half g_Q     [(size_t)M4  * 512];
__device__ __half g_XMSG  [(size_t)M12 * 256];
__device__ __half g_XAGG  [(size_t)M4  * 256];
__device__ __half g_FH    [(size_t)M4  * 512];

__device__ float  g_part  [2 * NCHUNK * 512];     // NCHUNK-layout partials
__device__ float  g_part2 [2 * GY4 * 512];        // CTA-layout partials (from GEMM epilogues)
__device__ float  g_bpart [8 * 512];              // bias fold partials
__device__ float  g_sbuf  [7 * 512];
__device__ float  g_tbuf  [7 * 512];
__device__ float  g_zero  [512];
__device__ float  g_bias  [7 * 512];

// folded half weights
__device__ __half g_Whn0 [256 * 512];
__device__ __half g_Whn1 [512 * 256];
__device__ __half g_Whp  [256 * 512];
__device__ __half g_Whq  [256 * 512];
__device__ __half g_Whm1 [512 * 256];
__device__ __half g_Whf0 [512 * 512];
__device__ __half g_Whf1 [512 * 256];

// ---------------- small kernels ----------------
// convert x->half AND accumulate column stats of the half values (one pass)
__global__ void cvt_colstats(const float* __restrict__ x, __half* __restrict__ xh,
                             float* __restrict__ part)
{
    int c = threadIdx.x;   // 256
    float sm = 0.f, ss = 0.f;
    for (int r = blockIdx.x; r < M4; r += NCHUNK) {
        __half h = __float2half(x[(size_t)r * 256 + c]);
        xh[(size_t)r * 256 + c] = h;
        float v = __half2float(h);
        sm += v; ss += v * v;
    }
    part[(size_t)blockIdx.x * 256 + c]            = sm;
    part[(size_t)(NCHUNK + blockIdx.x) * 256 + c] = ss;
}

// NCHUNK-layout final reduce + fold 3 BN sets (for input stats)
__global__ void nk_final_fold3(const float* __restrict__ part, int M,
    const float* g0, const float* b0, float* s0, float* t0,
    const float* g1, const float* b1, float* s1, float* t1,
    const float* g2, const float* b2, float* s2, float* t2)
{
    int c = threadIdx.x;  // 256
    float sm = 0.f, ss = 0.f;
    for (int i = 0; i < NCHUNK; ++i) {
        sm += part[(size_t)i * 256 + c];
        ss += part[(size_t)(NCHUNK + i) * 256 + c];
    }
    float m = sm / (float)M;
    float r = rsqrtf(ss / (float)M - m * m + EPS);
    { float sc = g0[c] * r; s0[c] = sc; t0[c] = b0[c] - m * sc; }
    { float sc = g1[c] * r; s1[c] = sc; t1[c] = b1[c] - m * sc; }
    { float sc = g2[c] * r; s2[c] = sc; t2[c] = b2[c] - m * sc; }
}

// NCHUNK-layout final reduce + fold (stride/coloff parametrized)
__global__ void nk_final_fold(const float* __restrict__ part, int stride, int coloff, int M,
    const float* __restrict__ g, const float* __restrict__ b,
    float* __restrict__ s, float* __restrict__ t)
{
    int c = threadIdx.x;
    float sm = 0.f, ss = 0.f;
    for (int i = 0; i < NCHUNK; ++i) {
        sm += part[(size_t)i * stride + coloff + c];
        ss += part[(size_t)(NCHUNK + i) * stride + coloff + c];
    }
    float m = sm / (float)M;
    float r = rsqrtf(ss / (float)M - m * m + EPS);
    float sc = g[c] * r;
    s[c] = sc;
    t[c] = b[c] - m * sc;
}

// CTA-layout (GY4-deep) final reduce + fold (from GEMM epilogue partials)
__global__ void cta_final_fold(const float* __restrict__ part2, int M,
    const float* __restrict__ g, const float* __restrict__ b,
    float* __restrict__ s, float* __restrict__ t)
{
    int c = threadIdx.x;
    float sm = 0.f, ss = 0.f;
    for (int i = 0; i < GY4; ++i) {
        sm += part2[(size_t)i * 512 + c];
        ss += part2[(size_t)(GY4 + i) * 512 + c];
    }
    float m = sm / (float)M;
    float r = rsqrtf(ss / (float)M - m * m + EPS);
    float sc = g[c] * r;
    s[c] = sc;
    t[c] = b[c] - m * sc;
}

__global__ void pqstats_partial(const __half* __restrict__ P, const __half* __restrict__ Q,
                                float* __restrict__ part)
{
    int c = threadIdx.x;  // 512
    float sm = 0.f, ss = 0.f;
    for (int b = blockIdx.x; b < BATCH; b += gridDim.x) {
        float pv[4], qv[4];
        #pragma unroll
        for (int i = 0; i < 4; ++i) {
            pv[i] = __half2float(P[((size_t)b * 4 + i) * 512 + c]);
            qv[i] = __half2float(Q[((size_t)b * 4 + i) * 512 + c]);
        }
        #pragma unroll
        for (int i = 0; i < 4; ++i)
            #pragma unroll
            for (int j = 0; j < 4; ++j)
                if (i != j) {
                    float v = fmaxf(pv[i] + qv[j], 0.f);
                    sm += v; ss += v * v;
                }
    }
    part[(size_t)blockIdx.x * 512 + c]            = sm;
    part[(size_t)(NCHUNK + blockIdx.x) * 512 + c] = ss;
}

// Wh[k][n] = half(W[k][n] * s[k])
__global__ void fold_w(const float* __restrict__ W, const float* __restrict__ s,
                       __half* __restrict__ Wh, int N)
{
    int idx = blockIdx.x * blockDim.x + threadIdx.x;
    int k = idx / N;
    Wh[idx] = __float2half(W[idx] * s[k]);
}

// bias fold phase A: bp[kg][n] = sum_{k in group} t[k]*W[k][n]   grid(N/128, 8), block 128
__global__ void fold_bias_part(const float* __restrict__ W, const float* __restrict__ t,
                               float* __restrict__ bp, int K, int N)
{
    int n  = blockIdx.x * 128 + threadIdx.x;
    int kg = blockIdx.y;
    int kn = K >> 3;
    int k0 = kg * kn;
    float a = 0.f;
    for (int k = k0; k < k0 + kn; ++k) a += t[k] * W[(size_t)k * N + n];
    bp[kg * 512 + n] = a;
}
// bias fold phase B: bout[n] = c[n] + sum_kg bp[kg][n]    block N threads
__global__ void fold_bias_final(const float* __restrict__ bp, const float* __restrict__ c,
                                float* __restrict__ bout)
{
    int n = threadIdx.x;
    float a = c[n];
    #pragma unroll
    for (int kg = 0; kg < 8; ++kg) a += bp[kg * 512 + n];
    bout[n] = a;
}

// avg3 + column stats of XAGG (writes part at stride 512, coloff 256)
__global__ void avg3_stats(const __half* __restrict__ XMSG, __half* __restrict__ XAGG,
                           float* __restrict__ part)
{
    int c = threadIdx.x;   // 256
    const float inv3 = 1.f / 3.f;
    float sm = 0.f, ss = 0.f;
    for (int bi = blockIdx.x; bi < M4; bi += NCHUNK) {
        size_t base = (size_t)bi * 3 * 256 + c;
        float a = __half2float(XMSG[base]);
        float b = __half2float(XMSG[base + 256]);
        float d = __half2float(XMSG[base + 512]);
        __half h = __float2half((a + b + d) * inv3);
        XAGG[(size_t)bi * 256 + c] = h;
        float v = __half2float(h);
        sm += v; ss += v * v;
    }
    part[(size_t)blockIdx.x * 512 + 256 + c]            = sm;
    part[(size_t)(NCHUNK + blockIdx.x) * 512 + 256 + c] = ss;
}

// ---------------- fp16 mma GEMM -----------------------------------------------
// C[M,N] = epi( A[M,K] @ Wh[K,N] + bias )    (BN folded into Wh/bias)
// AMODE 0 plain, 1 relu(P+Q) gather, 2 concat(A,A2)
// EPI 0 none, 1 relu, 2 sigmoid.  OTYPE 0 half, 1 float.
// STAT 1: write per-CTA column sum/sumsq partials to part2 (CTA layout, stride 512)
#define NSTAGE 4
#define A_ST  (64 * APADH)
#define B_ST  (32 * BPADH)
#define SHM_BYTES ((NSTAGE * (A_ST + B_ST)) * 2)

template<int AMODE>
__device__ __forceinline__ void stageA(uint32_t uAbuf, __half* smAbuf,
                                       const __half* __restrict__ A,
                                       const __half* __restrict__ A2,
                                       int row0, int kbase, int K, int tid)
{
    if (AMODE != 1) {
        #pragma unroll
        for (int p = 0; p < 2; ++p) {
            int lin = p * 128 + tid;
            int row = lin >> 2;
            int c8  = lin & 3;
            int gk  = kbase + c8 * 8;
            const __half* src;
            if (AMODE == 0) src = &A[(size_t)(row0 + row) * K + gk];
            else src = (gk < 256) ? &A [(size_t)(row0 + row) * 256 + gk]
                                  : &A2[(size_t)(row0 + row) * 256 + gk - 256];
            cp16(uAbuf + (uint32_t)(row * APADH + c8 * 8) * 2u, src);
        }
    } else {
        const __half2 z2 = __float2half2_rn(0.f);
        #pragma unroll
        for (int p = 0; p < 2; ++p) {
            int lin = p * 128 + tid;
            int row = lin >> 2;
            int c8  = lin & 3;
            int gr  = row0 + row;
            int b   = gr / 12;
            int rem = gr - b * 12;
            int i   = rem / 3;
            int jj  = rem - i * 3;
            int j   = jj + (jj >= i);
            int gk  = kbase + c8 * 8;
            uint4 pv4 = *reinterpret_cast<const uint4*>(&A [((size_t)b * 4 + i) * 512 + gk]);
            uint4 qv4 = *reinterpret_cast<const uint4*>(&A2[((size_t)b * 4 + j) * 512 + gk]);
            const __half2* ph = reinterpret_cast<const __half2*>(&pv4);
            const __half2* qh = reinterpret_cast<const __half2*>(&qv4);
            __half2 o[4];
            #pragma unroll
            for (int q = 0; q < 4; ++q)
                o[q] = __hmax2(__hadd2(ph[q], qh[q]), z2);
            *reinterpret_cast<uint4*>(&smAbuf[row * APADH + c8 * 8]) =
                *reinterpret_cast<uint4*>(o);
        }
    }
}

__device__ __forceinline__ void stageB(uint32_t uBbuf, const __half* __restrict__ Wh,
                                       int colblk, int kbase, int N, int tid)
{
    #pragma unroll
    for (int p = 0; p < 8; ++p) {
        int lin = p * 128 + tid;
        int k   = lin >> 5;
        int c8  = lin & 31;
        cp16(uBbuf + (uint32_t)(k * BPADH + c8 * 8) * 2u,
             &Wh[(size_t)(kbase + k) * N + colblk + c8 * 8]);
    }
}

template<int AMODE, int EPI, int OTYPE, int STAT>
__global__ void __launch_bounds__(128, 2)
gemm_h(const __half* __restrict__ A, const __half* __restrict__ A2,
       const __half* __restrict__ Wh, const float* __restrict__ bias,
       void* __restrict__ Cout, float* __restrict__ part2, int K, int N)
{
    extern __shared__ __half sm[];
    __half* smA = sm;
    __half* smB = sm + NSTAGE * A_ST;
    const uint32_t uA = smem_u32(smA);
    const uint32_t uB = smem_u32(smB);

    const int tid    = threadIdx.x;
    const int lane   = tid & 31;
    const int wn     = tid >> 5;
    const int row0   = blockIdx.y * 64;
    const int colblk = blockIdx.x * 256;

    float acc[4][8][4];
    #pragma unroll
    for (int a = 0; a < 4; ++a)
        #pragma unroll
        for (int b = 0; b < 8; ++b)
            #pragma unroll
            for (int q = 0; q < 4; ++q) acc[a][b][q] = 0.f;

    const int NC = K >> 5;
    #pragma unroll
    for (int s = 0; s < 3; ++s) {
        stageA<AMODE>(uA + (uint32_t)(s * A_ST) * 2u, smA + s * A_ST, A, A2, row0, s * 32, K, tid);
        stageB(uB + (uint32_t)(s * B_ST) * 2u, Wh, colblk, s * 32, N, tid);
        asm volatile("cp.async.commit_group;");
    }

    const int aLrow = ((lane >> 3) & 1) * 8 + (lane & 7);
    const int aLcol = (lane >> 4) * 8;
    const int lm    = lane >> 3;
    const int lrow  = (lane & 7) + (lm & 1) * 8;
    const int lcol  = (lm >> 1) * 8;

    for (int c = 0; c < NC; ++c) {
        asm volatile("cp.async.wait_group 2;");
        __syncthreads();
        if (c + 3 < NC) {
            int s = (c + 3) & (NSTAGE - 1);
            stageA<AMODE>(uA + (uint32_t)(s * A_ST) * 2u, smA + s * A_ST, A, A2, row0, (c + 3) * 32, K, tid);
            stageB(uB + (uint32_t)(s * B_ST) * 2u, Wh, colblk, (c + 3) * 32, N, tid);
        }
        asm volatile("cp.async.commit_group;");

        const int sb = c & (NSTAGE - 1);
        const uint32_t cA = uA + (uint32_t)(sb * A_ST) * 2u;
        const uint32_t cB = uB + (uint32_t)(sb * B_ST) * 2u;

        #pragma unroll
        for (int s = 0; s < 2; ++s) {
            const int kloc = s * 16;
            uint32_t bf[8][2];
            #pragma unroll
            for (int ntt = 0; ntt < 4; ++ntt) {
                uint32_t r[4];
                uint32_t addr = cB + (uint32_t)((kloc + lrow) * BPADH
                                 + wn * 64 + ntt * 16 + lcol) * 2u;
                ldmx4t(r, addr);
                bf[ntt * 2][0]     = r[0];
                bf[ntt * 2][1]     = r[1];
                bf[ntt * 2 + 1][0] = r[2];
                bf[ntt * 2 + 1][1] = r[3];
            }
            #pragma unroll
            for (int mt = 0; mt < 4; ++mt) {
                uint32_t af[4];
                uint32_t addr = cA + (uint32_t)((mt * 16 + aLrow) * APADH + kloc + aLcol) * 2u;
                ldmx4(af, addr);
                #pragma unroll
                for (int nt = 0; nt < 8; ++nt)
                    mma16816(acc[mt][nt], af, bf[nt]);
            }
        }
    }

    // ---- epilogue (+ optional fused column stats)
    float cs[8][2], cq[8][2];
    if (STAT) {
        #pragma unroll
        for (int nt = 0; nt < 8; ++nt) { cs[nt][0]=cs[nt][1]=cq[nt][0]=cq[nt][1]=0.f; }
    }
    #pragma unroll
    for (int mt = 0; mt < 4; ++mt) {
        int r0 = row0 + mt * 16 + (lane >> 2);
        #pragma unroll
        for (int nt = 0; nt < 8; ++nt) {
            int col = colblk + wn * 64 + nt * 8 + (lane & 3) * 2;
            float b0 = bias[col], b1 = bias[col + 1];
            float v0 = acc[mt][nt][0] + b0;
            float v1 = acc[mt][nt][1] + b1;
            float v2 = acc[mt][nt][2] + b0;
            float v3 = acc[mt][nt][3] + b1;
            if (EPI == 1) {
                v0 = fmaxf(v0, 0.f); v1 = fmaxf(v1, 0.f);
                v2 = fmaxf(v2, 0.f); v3 = fmaxf(v3, 0.f);
            } else if (EPI == 2) {
                v0 = 1.f / (1.f + __expf(-v0));
                v1 = 1.f / (1.f + __expf(-v1));
                v2 = 1.f / (1.f + __expf(-v2));
                v3 = 1.f / (1.f + __expf(-v3));
            }
            if (STAT) {
                cs[nt][0] += v0 + v2;           cs[nt][1] += v1 + v3;
                cq[nt][0] += v0 * v0 + v2 * v2; cq[nt][1] += v1 * v1 + v3 * v3;
            }
            if (OTYPE == 0) {
                __half* C = (__half*)Cout;
                *reinterpret_cast<__half2*>(&C[(size_t)r0 * N + col])       = __floats2half2_rn(v0, v1);
                *reinterpret_cast<__half2*>(&C[(size_t)(r0 + 8) * N + col]) = __floats2half2_rn(v2, v3);
            } else {
                float* C = (float*)Cout;
                *reinterpret_cast<float2*>(&C[(size_t)r0 * N + col])       = make_float2(v0, v1);
                *reinterpret_cast<float2*>(&C[(size_t)(r0 + 8) * N + col]) = make_float2(v2, v3);
            }
        }
    }
    if (STAT) {
        // reduce over the 8 row-groups (lane bits 2..4)
        #pragma unroll
        for (int nt = 0; nt < 8; ++nt)
            #pragma unroll
            for (int p = 0; p < 2; ++p) {
                #pragma unroll
                for (int off = 4; off < 32; off <<= 1) {
                    cs[nt][p] += __shfl_xor_sync(0xFFFFFFFF, cs[nt][p], off);
                    cq[nt][p] += __shfl_xor_sync(0xFFFFFFFF, cq[nt][p], off);
                }
            }
        if ((lane >> 2) == 0) {
            #pragma unroll
            for (int nt = 0; nt < 8; ++nt) {
                int col = colblk + wn * 64 + nt * 8 + (lane & 3) * 2;
                part2[(size_t)blockIdx.y * 512 + col]           = cs[nt][0];
                part2[(size_t)blockIdx.y * 512 + col + 1]       = cs[nt][1];
                part2[(size_t)(GY4 + blockIdx.y) * 512 + col]     = cq[nt][0];
                part2[(size_t)(GY4 + blockIdx.y) * 512 + col + 1] = cq[nt][1];
            }
        }
    }
}

// ---------------- launch ----------------
template<typename Tp>
static inline Tp* sym(const void* symbol)
{
    void* p = nullptr;
    cudaGetSymbolAddress(&p, symbol);
    return (Tp*)p;
}

extern "C" void kernel_launch(void* const* d_in, const int* in_sizes, int n_in,
                              void* d_out, int out_size)
{
    const float* x   = (const float*)d_in[0];
    const float* ng0 = (const float*)d_in[1];
    const float* nb0 = (const float*)d_in[2];
    const float* nW0 = (const float*)d_in[3];
    const float* nc0 = (const float*)d_in[4];
    const float* ng1 = (const float*)d_in[5];
    const float* nb1 = (const float*)d_in[6];
    const float* nW1 = (const float*)d_in[7];
    const float* nc1 = (const float*)d_in[8];
    const float* mg0 = (const float*)d_in[9];
    const float* mb0 = (const float*)d_in[10];
    const float* mW0 = (const float*)d_in[11];
    const float* mc0 = (const float*)d_in[12];
    const float* mg1 = (const float*)d_in[13];
    const float* mb1 = (const float*)d_in[14];
    const float* mW1 = (const float*)d_in[15];
    const float* mc1 = (const float*)d_in[16];
    const float* fg0 = (const float*)d_in[17];
    const float* fb0 = (const float*)d_in[18];
    const float* fW0 = (const float*)d_in[19];
    const float* fc0 = (const float*)d_in[20];
    const float* fg1 = (const float*)d_in[21];
    const float* fb1 = (const float*)d_in[22];
    const float* fW1 = (const float*)d_in[23];
    const float* fc1 = (const float*)d_in[24];
    float* out = (float*)d_out;

    __half* xh    = sym<__half>(g_xh);
    __half* XNH   = sym<__half>(g_XNH);
    __half* XNODE = sym<__half>(g_XNODE);
    __half* P     = sym<__half>(g_P);
    __half* Q     = sym<__half>(g_Q);
    __half* XMSG  = sym<__half>(g_XMSG);
    __half* XAGG  = sym<__half>(g_XAGG);
    __half* FH    = sym<__half>(g_FH);
    float*  part  = sym<float >(g_part);
    float*  part2 = sym<float >(g_part2);
    float*  bpart = sym<float >(g_bpart);
    float*  S     = sym<float >(g_sbuf);
    float*  T     = sym<float >(g_tbuf);
    float*  zero  = sym<float >(g_zero);
    float*  BI    = sym<float >(g_bias);

    __half* Whn0 = sym<__half>(g_Whn0);
    __half* Whn1 = sym<__half>(g_Whn1);
    __half* Whp  = sym<__half>(g_Whp);
    __half* Whq  = sym<__half>(g_Whq);
    __half* Whm1 = sym<__half>(g_Whm1);
    __half* Whf0 = sym<__half>(g_Whf0);
    __half* Whf1 = sym<__half>(g_Whf1);

    float *s_n0 = S + 0*512, *t_n0 = T + 0*512, *b_n0 = BI + 0*512;
    float *s_n1 = S + 1*512, *t_n1 = T + 1*512, *b_n1 = BI + 1*512;
    float *s_p  = S + 2*512, *t_p  = T + 2*512, *b_p  = BI + 2*512;
    float *s_q  = S + 3*512, *t_q  = T + 3*512, *b_q  = BI + 3*512;
    float *s_m1 = S + 4*512, *t_m1 = T + 4*512, *b_m1 = BI + 4*512;
    float *s_f0 = S + 5*512, *t_f0 = T + 5*512, *b_f0 = BI + 5*512;
    float *s_f1 = S + 6*512, *t_f1 = T + 6*512, *b_f1 = BI + 6*512;

    cudaFuncSetAttribute(gemm_h<0,1,0,1>, cudaFuncAttributeMaxDynamicSharedMemorySize, SHM_BYTES);
    cudaFuncSetAttribute(gemm_h<0,2,0,1>, cudaFuncAttributeMaxDynamicSharedMemorySize, SHM_BYTES);
    cudaFuncSetAttribute(gemm_h<0,0,0,0>, cudaFuncAttributeMaxDynamicSharedMemorySize, SHM_BYTES);
    cudaFuncSetAttribute(gemm_h<1,2,0,0>, cudaFuncAttributeMaxDynamicSharedMemorySize, SHM_BYTES);
    cudaFuncSetAttribute(gemm_h<2,1,0,1>, cudaFuncAttributeMaxDynamicSharedMemorySize, SHM_BYTES);
    cudaFuncSetAttribute(gemm_h<0,2,1,0>, cudaFuncAttributeMaxDynamicSharedMemorySize, SHM_BYTES);

    // ---- input convert + stats (one pass)
    cvt_colstats<<<NCHUNK, 256>>>(x, xh, part);
    nk_final_fold3<<<1, 256>>>(part, M4,
        ng0, nb0, s_n0, t_n0,
        mg0, mb0, s_p,  t_p,
        mg0 + 256, mb0 + 256, s_q, t_q);
    fold_w<<<256*512/256, 256>>>(nW0,             s_n0, Whn0, 512);
    fold_w<<<256*512/256, 256>>>(mW0,             s_p,  Whp,  512);
    fold_w<<<256*512/256, 256>>>(mW0 + 256 * 512, s_q,  Whq,  512);
    fold_bias_part<<<dim3(4, 8), 128>>>(nW0,             t_n0, bpart, 256, 512);
    fold_bias_final<<<1, 512>>>(bpart, nc0, b_n0);
    fold_bias_part<<<dim3(4, 8), 128>>>(mW0,             t_p,  bpart, 256, 512);
    fold_bias_final<<<1, 512>>>(bpart, zero, b_p);
    fold_bias_part<<<dim3(4, 8), 128>>>(mW0 + 256 * 512, t_q,  bpart, 256, 512);
    fold_bias_final<<<1, 512>>>(bpart, mc0, b_q);

    // ---- node MLP (stats fused into epilogues)
    gemm_h<0,1,0,1><<<dim3(2, GY4), 128, SHM_BYTES>>>(xh, nullptr, Whn0, b_n0, XNH, part2, 256, 512);
    cta_final_fold<<<1, 512>>>(part2, M4, ng1, nb1, s_n1, t_n1);
    fold_w<<<512*256/256, 256>>>(nW1, s_n1, Whn1, 256);
    fold_bias_part<<<dim3(2, 8), 128>>>(nW1, t_n1, bpart, 512, 256);
    fold_bias_final<<<1, 256>>>(bpart, nc1, b_n1);
    gemm_h<0,2,0,1><<<dim3(1, GY4), 128, SHM_BYTES>>>(XNH, nullptr, Whn1, b_n1, XNODE, part2, 512, 256);

    // ---- msg MLP layer-0 via P/Q factorization
    gemm_h<0,0,0,0><<<dim3(2, GY4), 128, SHM_BYTES>>>(xh, nullptr, Whp, b_p, P, nullptr, 256, 512);
    gemm_h<0,0,0,0><<<dim3(2, GY4), 128, SHM_BYTES>>>(xh, nullptr, Whq, b_q, Q, nullptr, 256, 512);

    // ---- msg hidden stats (HM never materialized)
    pqstats_partial<<<NCHUNK, 512>>>(P, Q, part);
    nk_final_fold<<<1, 512>>>(part, 512, 0, M12, mg1, mb1, s_m1, t_m1);
    fold_w<<<512*256/256, 256>>>(mW1, s_m1, Whm1, 256);
    fold_bias_part<<<dim3(2, 8), 128>>>(mW1, t_m1, bpart, 512, 256);
    fold_bias_final<<<1, 256>>>(bpart, mc1, b_m1);

    // ---- msg MLP layer-1, A = relu(P+Q) on the fly
    gemm_h<1,2,0,0><<<dim3(1, M12/64), 128, SHM_BYTES>>>(P, Q, Whm1, b_m1, XMSG, nullptr, 512, 256);
    avg3_stats<<<NCHUNK, 256>>>(XMSG, XAGG, part);

    // ---- final MLP, A = concat(XNODE, XAGG) on the fly
    // s_f0[0:256] from XNODE epilogue partials (CTA layout), s_f0[256:512] from avg3 (NCHUNK layout)
    cta_final_fold<<<1, 256>>>(part2, M4, fg0, fb0, s_f0, t_f0);
    nk_final_fold<<<1, 256>>>(part, 512, 256, M4, fg0 + 256, fb0 + 256, s_f0 + 256, t_f0 + 256);
    fold_w<<<512*512/256, 256>>>(fW0, s_f0, Whf0, 512);
    fold_bias_part<<<dim3(4, 8), 128>>>(fW0, t_f0, bpart, 512, 512);
    fold_bias_final<<<1, 512>>>(bpart, fc0, b_f0);
    gemm_h<2,1,0,1><<<dim3(2, GY4), 128, SHM_BYTES>>>(XNODE, XAGG, Whf0, b_f0, FH, part2, 512, 512);
    cta_final_fold<<<1, 512>>>(part2, M4, fg1, fb1, s_f1, t_f1);
    fold_w<<<512*256/256, 256>>>(fW1, s_f1, Whf1, 256);
    fold_bias_part<<<dim3(2, 8), 128>>>(fW1, t_f1, bpart, 512, 256);
    fold_bias_final<<<1, 256>>>(bpart, fc1, b_f1);
    gemm_h<0,2,1,0><<<dim3(1, GY4), 128, SHM_BYTES>>>(FH, nullptr, Whf1, b_f1, out, nullptr, 512, 256);
}

// round 9
// speedup vs baseline: 4.4454x; 1.1512x over previous
#include <cuda_runtime.h>
#include <cuda_fp16.h>
#include <cstdint>
#include <math.h>

// ---------------- problem constants ----------------
#define BATCH   16384
#define M4      65536
#define M12     196608
#define EPS     1e-5f
#define NCHUNK  256
#define GY4     (M4 / 64)

#define APADH 40
#define BPADH 264

// ---------------- PTX helpers (plain sm_80+ PTX only) ----------------
__device__ __forceinline__ void cp16(uint32_t dst, const void* src) {
    asm volatile("cp.async.cg.shared.global [%0], [%1], 16;" :: "r"(dst), "l"(src));
}
__device__ __forceinline__ uint32_t smem_u32(const void* p) {
    uint32_t a;
    asm("{ .reg .u64 t; cvta.to.shared.u64 t, %1; cvt.u32.u64 %0, t; }" : "=r"(a) : "l"(p));
    return a;
}
__device__ __forceinline__ void mma16816(float* c, const uint32_t* a, const uint32_t* b) {
    asm volatile(
        "mma.sync.aligned.m16n8k16.row.col.f32.f16.f16.f32 "
        "{%0,%1,%2,%3},{%4,%5,%6,%7},{%8,%9},{%0,%1,%2,%3};"
        : "+f"(c[0]), "+f"(c[1]), "+f"(c[2]), "+f"(c[3])
        : "r"(a[0]), "r"(a[1]), "r"(a[2]), "r"(a[3]), "r"(b[0]), "r"(b[1]));
}
__device__ __forceinline__ void ldmx4(uint32_t* r, uint32_t addr) {
    asm volatile("ldmatrix.sync.aligned.m8n8.x4.shared.b16 {%0,%1,%2,%3}, [%4];"
        : "=r"(r[0]), "=r"(r[1]), "=r"(r[2]), "=r"(r[3]) : "r"(addr));
}
__device__ __forceinline__ void ldmx4t(uint32_t* r, uint32_t addr) {
    asm volatile("ldmatrix.sync.aligned.m8n8.x4.trans.shared.b16 {%0,%1,%2,%3}, [%4];"
        : "=r"(r[0]), "=r"(r[1]), "=r"(r[2]), "=r"(r[3]) : "r"(addr));
}

// ---------------- static scratch ----------------
__device__ __half g_xh    [(size_t)M4  * 256];
__device__ __half g_XNH   [(size_t)M4  * 512];
__device__ __half g_XNODE [(size_t)M4  * 256];
__device__ __half g_P     [(size_t)M4  * 512];
__device__ __half g_Q     [(size_t)M4  * 512];
__device__ __half g_XMSG  [(size_t)M12 * 256];
__device__ __half g_XAGG  [(size_t)M4  * 256];
__device__ __half g_FH    [(size_t)M4  * 512];

__device__ float  g_part  [2 * NCHUNK * 512];
__device__ float  g_part2 [2 * GY4 * 512];
__device__ float  g_bpart [2 * 8 * 512];          // slice 0: msg stream, slice 1: node stream
__device__ float  g_sbuf  [7 * 512];
__device__ float  g_tbuf  [7 * 512];
__device__ float  g_zero  [512];
__device__ float  g_bias  [7 * 512];

__device__ __half g_Whn0 [256 * 512];
__device__ __half g_Whn1 [512 * 256];
__device__ __half g_Whp  [256 * 512];
__device__ __half g_Whq  [256 * 512];
__device__ __half g_Whm1 [512 * 256];
__device__ __half g_Whf0 [512 * 512];
__device__ __half g_Whf1 [512 * 256];

// ---------------- small kernels ----------------
__global__ void cvt_colstats(const float* __restrict__ x, __half* __restrict__ xh,
                             float* __restrict__ part)
{
    int c = threadIdx.x;   // 256
    float sm = 0.f, ss = 0.f;
    for (int r = blockIdx.x; r < M4; r += NCHUNK) {
        __half h = __float2half(x[(size_t)r * 256 + c]);
        xh[(size_t)r * 256 + c] = h;
        float v = __half2float(h);
        sm += v; ss += v * v;
    }
    part[(size_t)blockIdx.x * 256 + c]            = sm;
    part[(size_t)(NCHUNK + blockIdx.x) * 256 + c] = ss;
}

__global__ void nk_final_fold3(const float* __restrict__ part, int M,
    const float* g0, const float* b0, float* s0, float* t0,
    const float* g1, const float* b1, float* s1, float* t1,
    const float* g2, const float* b2, float* s2, float* t2)
{
    int c = threadIdx.x;  // 256
    float sm = 0.f, ss = 0.f;
    for (int i = 0; i < NCHUNK; ++i) {
        sm += part[(size_t)i * 256 + c];
        ss += part[(size_t)(NCHUNK + i) * 256 + c];
    }
    float m = sm / (float)M;
    float r = rsqrtf(ss / (float)M - m * m + EPS);
    { float sc = g0[c] * r; s0[c] = sc; t0[c] = b0[c] - m * sc; }
    { float sc = g1[c] * r; s1[c] = sc; t1[c] = b1[c] - m * sc; }
    { float sc = g2[c] * r; s2[c] = sc; t2[c] = b2[c] - m * sc; }
}

__global__ void nk_final_fold(const float* __restrict__ part, int stride, int coloff, int M,
    const float* __restrict__ g, const float* __restrict__ b,
    float* __restrict__ s, float* __restrict__ t)
{
    int c = threadIdx.x;
    float sm = 0.f, ss = 0.f;
    for (int i = 0; i < NCHUNK; ++i) {
        sm += part[(size_t)i * stride + coloff + c];
        ss += part[(size_t)(NCHUNK + i) * stride + coloff + c];
    }
    float m = sm / (float)M;
    float r = rsqrtf(ss / (float)M - m * m + EPS);
    float sc = g[c] * r;
    s[c] = sc;
    t[c] = b[c] - m * sc;
}

__global__ void cta_final_fold(const float* __restrict__ part2, int M,
    const float* __restrict__ g, const float* __restrict__ b,
    float* __restrict__ s, float* __restrict__ t)
{
    int c = threadIdx.x;
    float sm = 0.f, ss = 0.f;
    for (int i = 0; i < GY4; ++i) {
        sm += part2[(size_t)i * 512 + c];
        ss += part2[(size_t)(GY4 + i) * 512 + c];
    }
    float m = sm / (float)M;
    float r = rsqrtf(ss / (float)M - m * m + EPS);
    float sc = g[c] * r;
    s[c] = sc;
    t[c] = b[c] - m * sc;
}

__global__ void pqstats_partial(const __half* __restrict__ P, const __half* __restrict__ Q,
                                float* __restrict__ part)
{
    int c = threadIdx.x;  // 512
    float sm = 0.f, ss = 0.f;
    for (int b = blockIdx.x; b < BATCH; b += gridDim.x) {
        float pv[4], qv[4];
        #pragma unroll
        for (int i = 0; i < 4; ++i) {
            pv[i] = __half2float(P[((size_t)b * 4 + i) * 512 + c]);
            qv[i] = __half2float(Q[((size_t)b * 4 + i) * 512 + c]);
        }
        #pragma unroll
        for (int i = 0; i < 4; ++i)
            #pragma unroll
            for (int j = 0; j < 4; ++j)
                if (i != j) {
                    float v = fmaxf(pv[i] + qv[j], 0.f);
                    sm += v; ss += v * v;
                }
    }
    part[(size_t)blockIdx.x * 512 + c]            = sm;
    part[(size_t)(NCHUNK + blockIdx.x) * 512 + c] = ss;
}

// fused: Wh[k][n] = half(W[k][n]*s[k])  AND  bp[kg][n] = sum_k t[k]*W[k][n]
__global__ void fold_wb(const float* __restrict__ W, const float* __restrict__ s,
                        const float* __restrict__ t,
                        __half* __restrict__ Wh, float* __restrict__ bp, int K, int N)
{
    int n  = blockIdx.x * 128 + threadIdx.x;
    int kg = blockIdx.y;
    int kn = K >> 3;
    int k0 = kg * kn;
    float a = 0.f;
    for (int k = k0; k < k0 + kn; ++k) {
        float w = W[(size_t)k * N + n];
        Wh[(size_t)k * N + n] = __float2half(w * s[k]);
        a += t[k] * w;
    }
    bp[kg * 512 + n] = a;
}

__global__ void fold_bias_final(const float* __restrict__ bp, const float* __restrict__ c,
                                float* __restrict__ bout)
{
    int n = threadIdx.x;
    float a = c[n];
    #pragma unroll
    for (int kg = 0; kg < 8; ++kg) a += bp[kg * 512 + n];
    bout[n] = a;
}

__global__ void avg3_stats(const __half* __restrict__ XMSG, __half* __restrict__ XAGG,
                           float* __restrict__ part)
{
    int c = threadIdx.x;   // 256
    const float inv3 = 1.f / 3.f;
    float sm = 0.f, ss = 0.f;
    for (int bi = blockIdx.x; bi < M4; bi += NCHUNK) {
        size_t base = (size_t)bi * 3 * 256 + c;
        float a = __half2float(XMSG[base]);
        float b = __half2float(XMSG[base + 256]);
        float d = __half2float(XMSG[base + 512]);
        __half h = __float2half((a + b + d) * inv3);
        XAGG[(size_t)bi * 256 + c] = h;
        float v = __half2float(h);
        sm += v; ss += v * v;
    }
    part[(size_t)blockIdx.x * 512 + 256 + c]            = sm;
    part[(size_t)(NCHUNK + blockIdx.x) * 512 + 256 + c] = ss;
}

// ---------------- fp16 mma GEMM -----------------------------------------------
#define NSTAGE 4
#define A_ST  (64 * APADH)
#define B_ST  (32 * BPADH)
#define SHM_BYTES ((NSTAGE * (A_ST + B_ST)) * 2)

template<int AMODE>
__device__ __forceinline__ void stageA(uint32_t uAbuf, __half* smAbuf,
                                       const __half* __restrict__ A,
                                       const __half* __restrict__ A2,
                                       int row0, int kbase, int K, int tid)
{
    if (AMODE != 1) {
        #pragma unroll
        for (int p = 0; p < 2; ++p) {
            int lin = p * 128 + tid;
            int row = lin >> 2;
            int c8  = lin & 3;
            int gk  = kbase + c8 * 8;
            const __half* src;
            if (AMODE == 0) src = &A[(size_t)(row0 + row) * K + gk];
            else src = (gk < 256) ? &A [(size_t)(row0 + row) * 256 + gk]
                                  : &A2[(size_t)(row0 + row) * 256 + gk - 256];
            cp16(uAbuf + (uint32_t)(row * APADH + c8 * 8) * 2u, src);
        }
    } else {
        const __half2 z2 = __float2half2_rn(0.f);
        #pragma unroll
        for (int p = 0; p < 2; ++p) {
            int lin = p * 128 + tid;
            int row = lin >> 2;
            int c8  = lin & 3;
            int gr  = row0 + row;
            int b   = gr / 12;
            int rem = gr - b * 12;
            int i   = rem / 3;
            int jj  = rem - i * 3;
            int j   = jj + (jj >= i);
            int gk  = kbase + c8 * 8;
            uint4 pv4 = *reinterpret_cast<const uint4*>(&A [((size_t)b * 4 + i) * 512 + gk]);
            uint4 qv4 = *reinterpret_cast<const uint4*>(&A2[((size_t)b * 4 + j) * 512 + gk]);
            const __half2* ph = reinterpret_cast<const __half2*>(&pv4);
            const __half2* qh = reinterpret_cast<const __half2*>(&qv4);
            __half2 o[4];
            #pragma unroll
            for (int q = 0; q < 4; ++q)
                o[q] = __hmax2(__hadd2(ph[q], qh[q]), z2);
            *reinterpret_cast<uint4*>(&smAbuf[row * APADH + c8 * 8]) =
                *reinterpret_cast<uint4*>(o);
        }
    }
}

__device__ __forceinline__ void stageB(uint32_t uBbuf, const __half* __restrict__ Wh,
                                       int colblk, int kbase, int N, int tid)
{
    #pragma unroll
    for (int p = 0; p < 8; ++p) {
        int lin = p * 128 + tid;
        int k   = lin >> 5;
        int c8  = lin & 31;
        cp16(uBbuf + (uint32_t)(k * BPADH + c8 * 8) * 2u,
             &Wh[(size_t)(kbase + k) * N + colblk + c8 * 8]);
    }
}

template<int AMODE, int EPI, int OTYPE, int STAT>
__global__ void __launch_bounds__(128, 2)
gemm_h(const __half* __restrict__ A, const __half* __restrict__ A2,
       const __half* __restrict__ Wh, const float* __restrict__ bias,
       void* __restrict__ Cout, float* __restrict__ part2, int K, int N)
{
    extern __shared__ __half sm[];
    __half* smA = sm;
    __half* smB = sm + NSTAGE * A_ST;
    const uint32_t uA = smem_u32(smA);
    const uint32_t uB = smem_u32(smB);

    const int tid    = threadIdx.x;
    const int lane   = tid & 31;
    const int wn     = tid >> 5;
    const int row0   = blockIdx.y * 64;
    const int colblk = blockIdx.x * 256;

    float acc[4][8][4];
    #pragma unroll
    for (int a = 0; a < 4; ++a)
        #pragma unroll
        for (int b = 0; b < 8; ++b)
            #pragma unroll
            for (int q = 0; q < 4; ++q) acc[a][b][q] = 0.f;

    const int NC = K >> 5;
    #pragma unroll
    for (int s = 0; s < 3; ++s) {
        stageA<AMODE>(uA + (uint32_t)(s * A_ST) * 2u, smA + s * A_ST, A, A2, row0, s * 32, K, tid);
        stageB(uB + (uint32_t)(s * B_ST) * 2u, Wh, colblk, s * 32, N, tid);
        asm volatile("cp.async.commit_group;");
    }

    const int aLrow = ((lane >> 3) & 1) * 8 + (lane & 7);
    const int aLcol = (lane >> 4) * 8;
    const int lm    = lane >> 3;
    const int lrow  = (lane & 7) + (lm & 1) * 8;
    const int lcol  = (lm >> 1) * 8;

    for (int c = 0; c < NC; ++c) {
        asm volatile("cp.async.wait_group 2;");
        __syncthreads();
        if (c + 3 < NC) {
            int s = (c + 3) & (NSTAGE - 1);
            stageA<AMODE>(uA + (uint32_t)(s * A_ST) * 2u, smA + s * A_ST, A, A2, row0, (c + 3) * 32, K, tid);
            stageB(uB + (uint32_t)(s * B_ST) * 2u, Wh, colblk, (c + 3) * 32, N, tid);
        }
        asm volatile("cp.async.commit_group;");

        const int sb = c & (NSTAGE - 1);
        const uint32_t cA = uA + (uint32_t)(sb * A_ST) * 2u;
        const uint32_t cB = uB + (uint32_t)(sb * B_ST) * 2u;

        #pragma unroll
        for (int s = 0; s < 2; ++s) {
            const int kloc = s * 16;
            uint32_t bf[8][2];
            #pragma unroll
            for (int ntt = 0; ntt < 4; ++ntt) {
                uint32_t r[4];
                uint32_t addr = cB + (uint32_t)((kloc + lrow) * BPADH
                                 + wn * 64 + ntt * 16 + lcol) * 2u;
                ldmx4t(r, addr);
                bf[ntt * 2][0]     = r[0];
                bf[ntt * 2][1]     = r[1];
                bf[ntt * 2 + 1][0] = r[2];
                bf[ntt * 2 + 1][1] = r[3];
            }
            #pragma unroll
            for (int mt = 0; mt < 4; ++mt) {
                uint32_t af[4];
                uint32_t addr = cA + (uint32_t)((mt * 16 + aLrow) * APADH + kloc + aLcol) * 2u;
                ldmx4(af, addr);
                #pragma unroll
                for (int nt = 0; nt < 8; ++nt)
                    mma16816(acc[mt][nt], af, bf[nt]);
            }
        }
    }

    float cs[8][2], cq[8][2];
    if (STAT) {
        #pragma unroll
        for (int nt = 0; nt < 8; ++nt) { cs[nt][0]=cs[nt][1]=cq[nt][0]=cq[nt][1]=0.f; }
    }
    #pragma unroll
    for (int mt = 0; mt < 4; ++mt) {
        int r0 = row0 + mt * 16 + (lane >> 2);
        #pragma unroll
        for (int nt = 0; nt < 8; ++nt) {
            int col = colblk + wn * 64 + nt * 8 + (lane & 3) * 2;
            float b0 = bias[col], b1 = bias[col + 1];
            float v0 = acc[mt][nt][0] + b0;
            float v1 = acc[mt][nt][1] + b1;
            float v2 = acc[mt][nt][2] + b0;
            float v3 = acc[mt][nt][3] + b1;
            if (EPI == 1) {
                v0 = fmaxf(v0, 0.f); v1 = fmaxf(v1, 0.f);
                v2 = fmaxf(v2, 0.f); v3 = fmaxf(v3, 0.f);
            } else if (EPI == 2) {
                v0 = 1.f / (1.f + __expf(-v0));
                v1 = 1.f / (1.f + __expf(-v1));
                v2 = 1.f / (1.f + __expf(-v2));
                v3 = 1.f / (1.f + __expf(-v3));
            }
            if (STAT) {
                cs[nt][0] += v0 + v2;           cs[nt][1] += v1 + v3;
                cq[nt][0] += v0 * v0 + v2 * v2; cq[nt][1] += v1 * v1 + v3 * v3;
            }
            if (OTYPE == 0) {
                __half* C = (__half*)Cout;
                *reinterpret_cast<__half2*>(&C[(size_t)r0 * N + col])       = __floats2half2_rn(v0, v1);
                *reinterpret_cast<__half2*>(&C[(size_t)(r0 + 8) * N + col]) = __floats2half2_rn(v2, v3);
            } else {
                float* C = (float*)Cout;
                *reinterpret_cast<float2*>(&C[(size_t)r0 * N + col])       = make_float2(v0, v1);
                *reinterpret_cast<float2*>(&C[(size_t)(r0 + 8) * N + col]) = make_float2(v2, v3);
            }
        }
    }
    if (STAT) {
        #pragma unroll
        for (int nt = 0; nt < 8; ++nt)
            #pragma unroll
            for (int p = 0; p < 2; ++p) {
                #pragma unroll
                for (int off = 4; off < 32; off <<= 1) {
                    cs[nt][p] += __shfl_xor_sync(0xFFFFFFFF, cs[nt][p], off);
                    cq[nt][p] += __shfl_xor_sync(0xFFFFFFFF, cq[nt][p], off);
                }
            }
        if ((lane >> 2) == 0) {
            #pragma unroll
            for (int nt = 0; nt < 8; ++nt) {
                int col = colblk + wn * 64 + nt * 8 + (lane & 3) * 2;
                part2[(size_t)blockIdx.y * 512 + col]             = cs[nt][0];
                part2[(size_t)blockIdx.y * 512 + col + 1]         = cs[nt][1];
                part2[(size_t)(GY4 + blockIdx.y) * 512 + col]     = cq[nt][0];
                part2[(size_t)(GY4 + blockIdx.y) * 512 + col + 1] = cq[nt][1];
            }
        }
    }
}

// ---------------- launch ----------------
template<typename Tp>
static inline Tp* sym(const void* symbol)
{
    void* p = nullptr;
    cudaGetSymbolAddress(&p, symbol);
    return (Tp*)p;
}

extern "C" void kernel_launch(void* const* d_in, const int* in_sizes, int n_in,
                              void* d_out, int out_size)
{
    const float* x   = (const float*)d_in[0];
    const float* ng0 = (const float*)d_in[1];
    const float* nb0 = (const float*)d_in[2];
    const float* nW0 = (const float*)d_in[3];
    const float* nc0 = (const float*)d_in[4];
    const float* ng1 = (const float*)d_in[5];
    const float* nb1 = (const float*)d_in[6];
    const float* nW1 = (const float*)d_in[7];
    const float* nc1 = (const float*)d_in[8];
    const float* mg0 = (const float*)d_in[9];
    const float* mb0 = (const float*)d_in[10];
    const float* mW0 = (const float*)d_in[11];
    const float* mc0 = (const float*)d_in[12];
    const float* mg1 = (const float*)d_in[13];
    const float* mb1 = (const float*)d_in[14];
    const float* mW1 = (const float*)d_in[15];
    const float* mc1 = (const float*)d_in[16];
    const float* fg0 = (const float*)d_in[17];
    const float* fb0 = (const float*)d_in[18];
    const float* fW0 = (const float*)d_in[19];
    const float* fc0 = (const float*)d_in[20];
    const float* fg1 = (const float*)d_in[21];
    const float* fb1 = (const float*)d_in[22];
    const float* fW1 = (const float*)d_in[23];
    const float* fc1 = (const float*)d_in[24];
    float* out = (float*)d_out;

    __half* xh    = sym<__half>(g_xh);
    __half* XNH   = sym<__half>(g_XNH);
    __half* XNODE = sym<__half>(g_XNODE);
    __half* P     = sym<__half>(g_P);
    __half* Q     = sym<__half>(g_Q);
    __half* XMSG  = sym<__half>(g_XMSG);
    __half* XAGG  = sym<__half>(g_XAGG);
    __half* FH    = sym<__half>(g_FH);
    float*  part  = sym<float >(g_part);
    float*  part2 = sym<float >(g_part2);
    float*  bpart = sym<float >(g_bpart);
    float*  S     = sym<float >(g_sbuf);
    float*  T     = sym<float >(g_tbuf);
    float*  zero  = sym<float >(g_zero);
    float*  BI    = sym<float >(g_bias);

    __half* Whn0 = sym<__half>(g_Whn0);
    __half* Whn1 = sym<__half>(g_Whn1);
    __half* Whp  = sym<__half>(g_Whp);
    __half* Whq  = sym<__half>(g_Whq);
    __half* Whm1 = sym<__half>(g_Whm1);
    __half* Whf0 = sym<__half>(g_Whf0);
    __half* Whf1 = sym<__half>(g_Whf1);

    float* bpM = bpart;             // msg-stream bias partials
    float* bpN = bpart + 8 * 512;   // node-stream bias partials

    float *s_n0 = S + 0*512, *t_n0 = T + 0*512, *b_n0 = BI + 0*512;
    float *s_n1 = S + 1*512, *t_n1 = T + 1*512, *b_n1 = BI + 1*512;
    float *s_p  = S + 2*512, *t_p  = T + 2*512, *b_p  = BI + 2*512;
    float *s_q  = S + 3*512, *t_q  = T + 3*512, *b_q  = BI + 3*512;
    float *s_m1 = S + 4*512, *t_m1 = T + 4*512, *b_m1 = BI + 4*512;
    float *s_f0 = S + 5*512, *t_f0 = T + 5*512, *b_f0 = BI + 5*512;
    float *s_f1 = S + 6*512, *t_f1 = T + 6*512, *b_f1 = BI + 6*512;

    // one-time side stream + events (created on the non-captured correctness call)
    static cudaStream_t sN = nullptr;
    static cudaEvent_t  eF0 = nullptr, eNode = nullptr;
    if (!sN) {
        cudaStreamCreateWithFlags(&sN, cudaStreamNonBlocking);
        cudaEventCreateWithFlags(&eF0,   cudaEventDisableTiming);
        cudaEventCreateWithFlags(&eNode, cudaEventDisableTiming);
        cudaFuncSetAttribute(gemm_h<0,1,0,1>, cudaFuncAttributeMaxDynamicSharedMemorySize, SHM_BYTES);
        cudaFuncSetAttribute(gemm_h<0,2,0,1>, cudaFuncAttributeMaxDynamicSharedMemorySize, SHM_BYTES);
        cudaFuncSetAttribute(gemm_h<0,0,0,0>, cudaFuncAttributeMaxDynamicSharedMemorySize, SHM_BYTES);
        cudaFuncSetAttribute(gemm_h<1,2,0,0>, cudaFuncAttributeMaxDynamicSharedMemorySize, SHM_BYTES);
        cudaFuncSetAttribute(gemm_h<2,1,0,1>, cudaFuncAttributeMaxDynamicSharedMemorySize, SHM_BYTES);
        cudaFuncSetAttribute(gemm_h<0,2,1,0>, cudaFuncAttributeMaxDynamicSharedMemorySize, SHM_BYTES);
    }

    // ---- shared prologue (stream 0)
    cvt_colstats<<<NCHUNK, 256>>>(x, xh, part);
    nk_final_fold3<<<1, 256>>>(part, M4,
        ng0, nb0, s_n0, t_n0,
        mg0, mb0, s_p,  t_p,
        mg0 + 256, mb0 + 256, s_q, t_q);
    cudaEventRecord(eF0, 0);
    cudaStreamWaitEvent(sN, eF0, 0);

    // ---- node branch (stream sN)
    fold_wb<<<dim3(4, 8), 128, 0, sN>>>(nW0, s_n0, t_n0, Whn0, bpN, 256, 512);
    fold_bias_final<<<1, 512, 0, sN>>>(bpN, nc0, b_n0);
    gemm_h<0,1,0,1><<<dim3(2, GY4), 128, SHM_BYTES, sN>>>(xh, nullptr, Whn0, b_n0, XNH, part2, 256, 512);
    cta_final_fold<<<1, 512, 0, sN>>>(part2, M4, ng1, nb1, s_n1, t_n1);
    fold_wb<<<dim3(2, 8), 128, 0, sN>>>(nW1, s_n1, t_n1, Whn1, bpN, 512, 256);
    fold_bias_final<<<1, 256, 0, sN>>>(bpN, nc1, b_n1);
    gemm_h<0,2,0,1><<<dim3(1, GY4), 128, SHM_BYTES, sN>>>(XNH, nullptr, Whn1, b_n1, XNODE, part2, 512, 256);
    cta_final_fold<<<1, 256, 0, sN>>>(part2, M4, fg0, fb0, s_f0, t_f0);   // f0 first half
    cudaEventRecord(eNode, sN);

    // ---- msg branch (stream 0): p fold+final, then q fold+final (sequential, same slice)
    fold_wb<<<dim3(4, 8), 128>>>(mW0,             s_p, t_p, Whp, bpM, 256, 512);
    fold_bias_final<<<1, 512>>>(bpM, zero, b_p);
    fold_wb<<<dim3(4, 8), 128>>>(mW0 + 256 * 512, s_q, t_q, Whq, bpM, 256, 512);
    fold_bias_final<<<1, 512>>>(bpM, mc0, b_q);
    gemm_h<0,0,0,0><<<dim3(2, GY4), 128, SHM_BYTES>>>(xh, nullptr, Whp, b_p, P, nullptr, 256, 512);
    gemm_h<0,0,0,0><<<dim3(2, GY4), 128, SHM_BYTES>>>(xh, nullptr, Whq, b_q, Q, nullptr, 256, 512);
    pqstats_partial<<<NCHUNK, 512>>>(P, Q, part);
    nk_final_fold<<<1, 512>>>(part, 512, 0, M12, mg1, mb1, s_m1, t_m1);
    fold_wb<<<dim3(2, 8), 128>>>(mW1, s_m1, t_m1, Whm1, bpM, 512, 256);
    fold_bias_final<<<1, 256>>>(bpM, mc1, b_m1);
    gemm_h<1,2,0,0><<<dim3(1, M12/64), 128, SHM_BYTES>>>(P, Q, Whm1, b_m1, XMSG, nullptr, 512, 256);
    avg3_stats<<<NCHUNK, 256>>>(XMSG, XAGG, part);
    nk_final_fold<<<1, 256>>>(part, 512, 256, M4, fg0 + 256, fb0 + 256, s_f0 + 256, t_f0 + 256);

    // ---- join + final MLP (stream 0)
    cudaStreamWaitEvent(0, eNode, 0);
    fold_wb<<<dim3(4, 8), 128>>>(fW0, s_f0, t_f0, Whf0, bpM, 512, 512);
    fold_bias_final<<<1, 512>>>(bpM, fc0, b_f0);
    gemm_h<2,1,0,1><<<dim3(2, GY4), 128, SHM_BYTES>>>(XNODE, XAGG, Whf0, b_f0, FH, part2, 512, 512);
    cta_final_fold<<<1, 512>>>(part2, M4, fg1, fb1, s_f1, t_f1);
    fold_wb<<<dim3(2, 8), 128>>>(fW1, s_f1, t_f1, Whf1, bpM, 512, 256);
    fold_bias_final<<<1, 256>>>(bpM, fc1, b_f1);
    gemm_h<0,2,1,0><<<dim3(1, GY4), 128, SHM_BYTES>>>(FH, nullptr, Whf1, b_f1, out, nullptr, 512, 256);
}

// round 10
// speedup vs baseline: 4.4973x; 1.0117x over previous
#include <cuda_runtime.h>
#include <cuda_fp16.h>
#include <cstdint>
#include <math.h>

// ---------------- problem constants ----------------
#define BATCH   16384
#define M4      65536
#define M12     196608
#define EPS     1e-5f
#define NCHUNK  256
#define GY4     (M4 / 64)

#define APADH 40
#define BPADH 264

// ---------------- PTX helpers (plain sm_80+ PTX only) ----------------
__device__ __forceinline__ void cp16(uint32_t dst, const void* src) {
    asm volatile("cp.async.cg.shared.global [%0], [%1], 16;" :: "r"(dst), "l"(src));
}
__device__ __forceinline__ uint32_t smem_u32(const void* p) {
    uint32_t a;
    asm("{ .reg .u64 t; cvta.to.shared.u64 t, %1; cvt.u32.u64 %0, t; }" : "=r"(a) : "l"(p));
    return a;
}
__device__ __forceinline__ void mma16816(float* c, const uint32_t* a, const uint32_t* b) {
    asm volatile(
        "mma.sync.aligned.m16n8k16.row.col.f32.f16.f16.f32 "
        "{%0,%1,%2,%3},{%4,%5,%6,%7},{%8,%9},{%0,%1,%2,%3};"
        : "+f"(c[0]), "+f"(c[1]), "+f"(c[2]), "+f"(c[3])
        : "r"(a[0]), "r"(a[1]), "r"(a[2]), "r"(a[3]), "r"(b[0]), "r"(b[1]));
}
__device__ __forceinline__ void ldmx4(uint32_t* r, uint32_t addr) {
    asm volatile("ldmatrix.sync.aligned.m8n8.x4.shared.b16 {%0,%1,%2,%3}, [%4];"
        : "=r"(r[0]), "=r"(r[1]), "=r"(r[2]), "=r"(r[3]) : "r"(addr));
}
__device__ __forceinline__ void ldmx4t(uint32_t* r, uint32_t addr) {
    asm volatile("ldmatrix.sync.aligned.m8n8.x4.trans.shared.b16 {%0,%1,%2,%3}, [%4];"
        : "=r"(r[0]), "=r"(r[1]), "=r"(r[2]), "=r"(r[3]) : "r"(addr));
}

// ---------------- static scratch ----------------
__device__ __half g_xh    [(size_t)M4  * 256];
__device__ __half g_XNH   [(size_t)M4  * 512];
__device__ __half g_XNODE [(size_t)M4  * 256];
__device__ __half g_P     [(size_t)M4  * 512];
__device__ __half g_Q     [(size_t)M4  * 512];
__device__ __half g_XMSG  [(size_t)M12 * 256];
__device__ __half g_XAGG  [(size_t)M4  * 256];
__device__ __half g_FH    [(size_t)M4  * 512];

__device__ float  g_part  [2 * NCHUNK * 512];
__device__ float  g_part2 [2 * GY4 * 512];
__device__ float  g_bpart [7 * 8 * 512];          // per-stage bias partial slices
__device__ float  g_sbuf  [7 * 512];
__device__ float  g_tbuf  [7 * 512];
__device__ float  g_zero  [512];

__device__ __half g_Whn0 [256 * 512];
__device__ __half g_Whn1 [512 * 256];
__device__ __half g_Whp  [256 * 512];
__device__ __half g_Whq  [256 * 512];
__device__ __half g_Whm1 [512 * 256];
__device__ __half g_Whf0 [512 * 512];
__device__ __half g_Whf1 [512 * 256];

// ---------------- small kernels ----------------
__global__ void cvt_colstats(const float* __restrict__ x, __half* __restrict__ xh,
                             float* __restrict__ part)
{
    int c = threadIdx.x;   // 256
    float sm = 0.f, ss = 0.f;
    for (int r = blockIdx.x; r < M4; r += NCHUNK) {
        __half h = __float2half(x[(size_t)r * 256 + c]);
        xh[(size_t)r * 256 + c] = h;
        float v = __half2float(h);
        sm += v; ss += v * v;
    }
    part[(size_t)blockIdx.x * 256 + c]            = sm;
    part[(size_t)(NCHUNK + blockIdx.x) * 256 + c] = ss;
}

__global__ void nk_final_fold3(const float* __restrict__ part, int M,
    const float* g0, const float* b0, float* s0, float* t0,
    const float* g1, const float* b1, float* s1, float* t1,
    const float* g2, const float* b2, float* s2, float* t2)
{
    int c = threadIdx.x;  // 256
    float sm = 0.f, ss = 0.f;
    for (int i = 0; i < NCHUNK; ++i) {
        sm += part[(size_t)i * 256 + c];
        ss += part[(size_t)(NCHUNK + i) * 256 + c];
    }
    float m = sm / (float)M;
    float r = rsqrtf(ss / (float)M - m * m + EPS);
    { float sc = g0[c] * r; s0[c] = sc; t0[c] = b0[c] - m * sc; }
    { float sc = g1[c] * r; s1[c] = sc; t1[c] = b1[c] - m * sc; }
    { float sc = g2[c] * r; s2[c] = sc; t2[c] = b2[c] - m * sc; }
}

__global__ void nk_final_fold(const float* __restrict__ part, int stride, int coloff, int M,
    const float* __restrict__ g, const float* __restrict__ b,
    float* __restrict__ s, float* __restrict__ t)
{
    int c = threadIdx.x;
    float sm = 0.f, ss = 0.f;
    for (int i = 0; i < NCHUNK; ++i) {
        sm += part[(size_t)i * stride + coloff + c];
        ss += part[(size_t)(NCHUNK + i) * stride + coloff + c];
    }
    float m = sm / (float)M;
    float r = rsqrtf(ss / (float)M - m * m + EPS);
    float sc = g[c] * r;
    s[c] = sc;
    t[c] = b[c] - m * sc;
}

__global__ void cta_final_fold(const float* __restrict__ part2, int M,
    const float* __restrict__ g, const float* __restrict__ b,
    float* __restrict__ s, float* __restrict__ t)
{
    int c = threadIdx.x;
    float sm = 0.f, ss = 0.f;
    for (int i = 0; i < GY4; ++i) {
        sm += part2[(size_t)i * 512 + c];
        ss += part2[(size_t)(GY4 + i) * 512 + c];
    }
    float m = sm / (float)M;
    float r = rsqrtf(ss / (float)M - m * m + EPS);
    float sc = g[c] * r;
    s[c] = sc;
    t[c] = b[c] - m * sc;
}

__global__ void pqstats_partial(const __half* __restrict__ P, const __half* __restrict__ Q,
                                float* __restrict__ part)
{
    int c = threadIdx.x;  // 512
    float sm = 0.f, ss = 0.f;
    for (int b = blockIdx.x; b < BATCH; b += gridDim.x) {
        float pv[4], qv[4];
        #pragma unroll
        for (int i = 0; i < 4; ++i) {
            pv[i] = __half2float(P[((size_t)b * 4 + i) * 512 + c]);
            qv[i] = __half2float(Q[((size_t)b * 4 + i) * 512 + c]);
        }
        #pragma unroll
        for (int i = 0; i < 4; ++i)
            #pragma unroll
            for (int j = 0; j < 4; ++j)
                if (i != j) {
                    float v = fmaxf(pv[i] + qv[j], 0.f);
                    sm += v; ss += v * v;
                }
    }
    part[(size_t)blockIdx.x * 512 + c]            = sm;
    part[(size_t)(NCHUNK + blockIdx.x) * 512 + c] = ss;
}

// fused: Wh[k][n] = half(W[k][n]*s[k])  AND  bp[kg][n] = sum_k t[k]*W[k][n]
__global__ void fold_wb(const float* __restrict__ W, const float* __restrict__ s,
                        const float* __restrict__ t,
                        __half* __restrict__ Wh, float* __restrict__ bp, int K, int N)
{
    int n  = blockIdx.x * 128 + threadIdx.x;
    int kg = blockIdx.y;
    int kn = K >> 3;
    int k0 = kg * kn;
    float a = 0.f;
    for (int k = k0; k < k0 + kn; ++k) {
        float w = W[(size_t)k * N + n];
        Wh[(size_t)k * N + n] = __float2half(w * s[k]);
        a += t[k] * w;
    }
    bp[kg * 512 + n] = a;
}

__global__ void avg3_stats(const __half* __restrict__ XMSG, __half* __restrict__ XAGG,
                           float* __restrict__ part)
{
    int c = threadIdx.x;   // 256
    const float inv3 = 1.f / 3.f;
    float sm = 0.f, ss = 0.f;
    for (int bi = blockIdx.x; bi < M4; bi += NCHUNK) {
        size_t base = (size_t)bi * 3 * 256 + c;
        float a = __half2float(XMSG[base]);
        float b = __half2float(XMSG[base + 256]);
        float d = __half2float(XMSG[base + 512]);
        __half h = __float2half((a + b + d) * inv3);
        XAGG[(size_t)bi * 256 + c] = h;
        float v = __half2float(h);
        sm += v; ss += v * v;
    }
    part[(size_t)blockIdx.x * 512 + 256 + c]            = sm;
    part[(size_t)(NCHUNK + blockIdx.x) * 512 + 256 + c] = ss;
}

// ---------------- fp16 mma GEMM -----------------------------------------------
// bias computed in-kernel: bias[n] = cvec[n] + sum_{kg<8} bp[kg*512+n]
#define NSTAGE 4
#define A_ST  (64 * APADH)
#define B_ST  (32 * BPADH)
#define SHM_BYTES ((NSTAGE * (A_ST + B_ST)) * 2)

template<int AMODE>
__device__ __forceinline__ void stageA(uint32_t uAbuf, __half* smAbuf,
                                       const __half* __restrict__ A,
                                       const __half* __restrict__ A2,
                                       int row0, int kbase, int K, int tid)
{
    if (AMODE != 1) {
        #pragma unroll
        for (int p = 0; p < 2; ++p) {
            int lin = p * 128 + tid;
            int row = lin >> 2;
            int c8  = lin & 3;
            int gk  = kbase + c8 * 8;
            const __half* src;
            if (AMODE == 0) src = &A[(size_t)(row0 + row) * K + gk];
            else src = (gk < 256) ? &A [(size_t)(row0 + row) * 256 + gk]
                                  : &A2[(size_t)(row0 + row) * 256 + gk - 256];
            cp16(uAbuf + (uint32_t)(row * APADH + c8 * 8) * 2u, src);
        }
    } else {
        const __half2 z2 = __float2half2_rn(0.f);
        #pragma unroll
        for (int p = 0; p < 2; ++p) {
            int lin = p * 128 + tid;
            int row = lin >> 2;
            int c8  = lin & 3;
            int gr  = row0 + row;
            int b   = gr / 12;
            int rem = gr - b * 12;
            int i   = rem / 3;
            int jj  = rem - i * 3;
            int j   = jj + (jj >= i);
            int gk  = kbase + c8 * 8;
            uint4 pv4 = *reinterpret_cast<const uint4*>(&A [((size_t)b * 4 + i) * 512 + gk]);
            uint4 qv4 = *reinterpret_cast<const uint4*>(&A2[((size_t)b * 4 + j) * 512 + gk]);
            const __half2* ph = reinterpret_cast<const __half2*>(&pv4);
            const __half2* qh = reinterpret_cast<const __half2*>(&qv4);
            __half2 o[4];
            #pragma unroll
            for (int q = 0; q < 4; ++q)
                o[q] = __hmax2(__hadd2(ph[q], qh[q]), z2);
            *reinterpret_cast<uint4*>(&smAbuf[row * APADH + c8 * 8]) =
                *reinterpret_cast<uint4*>(o);
        }
    }
}

__device__ __forceinline__ void stageB(uint32_t uBbuf, const __half* __restrict__ Wh,
                                       int colblk, int kbase, int N, int tid)
{
    #pragma unroll
    for (int p = 0; p < 8; ++p) {
        int lin = p * 128 + tid;
        int k   = lin >> 5;
        int c8  = lin & 31;
        cp16(uBbuf + (uint32_t)(k * BPADH + c8 * 8) * 2u,
             &Wh[(size_t)(kbase + k) * N + colblk + c8 * 8]);
    }
}

template<int AMODE, int EPI, int OTYPE, int STAT>
__global__ void __launch_bounds__(128, 2)
gemm_h(const __half* __restrict__ A, const __half* __restrict__ A2,
       const __half* __restrict__ Wh,
       const float* __restrict__ cvec, const float* __restrict__ bp,
       void* __restrict__ Cout, float* __restrict__ part2, int K, int N)
{
    extern __shared__ __half sm[];
    __half* smA = sm;
    __half* smB = sm + NSTAGE * A_ST;
    const uint32_t uA = smem_u32(smA);
    const uint32_t uB = smem_u32(smB);

    const int tid    = threadIdx.x;
    const int lane   = tid & 31;
    const int wn     = tid >> 5;
    const int row0   = blockIdx.y * 64;
    const int colblk = blockIdx.x * 256;

    float acc[4][8][4];
    #pragma unroll
    for (int a = 0; a < 4; ++a)
        #pragma unroll
        for (int b = 0; b < 8; ++b)
            #pragma unroll
            for (int q = 0; q < 4; ++q) acc[a][b][q] = 0.f;

    const int NC = K >> 5;
    #pragma unroll
    for (int s = 0; s < 3; ++s) {
        stageA<AMODE>(uA + (uint32_t)(s * A_ST) * 2u, smA + s * A_ST, A, A2, row0, s * 32, K, tid);
        stageB(uB + (uint32_t)(s * B_ST) * 2u, Wh, colblk, s * 32, N, tid);
        asm volatile("cp.async.commit_group;");
    }

    const int aLrow = ((lane >> 3) & 1) * 8 + (lane & 7);
    const int aLcol = (lane >> 4) * 8;
    const int lm    = lane >> 3;
    const int lrow  = (lane & 7) + (lm & 1) * 8;
    const int lcol  = (lm >> 1) * 8;

    for (int c = 0; c < NC; ++c) {
        asm volatile("cp.async.wait_group 2;");
        __syncthreads();
        if (c + 3 < NC) {
            int s = (c + 3) & (NSTAGE - 1);
            stageA<AMODE>(uA + (uint32_t)(s * A_ST) * 2u, smA + s * A_ST, A, A2, row0, (c + 3) * 32, K, tid);
            stageB(uB + (uint32_t)(s * B_ST) * 2u, Wh, colblk, (c + 3) * 32, N, tid);
        }
        asm volatile("cp.async.commit_group;");

        const int sb = c & (NSTAGE - 1);
        const uint32_t cA = uA + (uint32_t)(sb * A_ST) * 2u;
        const uint32_t cB = uB + (uint32_t)(sb * B_ST) * 2u;

        #pragma unroll
        for (int s = 0; s < 2; ++s) {
            const int kloc = s * 16;
            // ---- batch ALL fragment loads for this k16 step first (ILP)
            uint32_t af[4][4];
            #pragma unroll
            for (int mt = 0; mt < 4; ++mt) {
                uint32_t addr = cA + (uint32_t)((mt * 16 + aLrow) * APADH + kloc + aLcol) * 2u;
                ldmx4(af[mt], addr);
            }
            uint32_t bf[8][2];
            #pragma unroll
            for (int ntt = 0; ntt < 4; ++ntt) {
                uint32_t r[4];
                uint32_t addr = cB + (uint32_t)((kloc + lrow) * BPADH
                                 + wn * 64 + ntt * 16 + lcol) * 2u;
                ldmx4t(r, addr);
                bf[ntt * 2][0]     = r[0];
                bf[ntt * 2][1]     = r[1];
                bf[ntt * 2 + 1][0] = r[2];
                bf[ntt * 2 + 1][1] = r[3];
            }
            // ---- then all 32 HMMAs back-to-back
            #pragma unroll
            for (int mt = 0; mt < 4; ++mt)
                #pragma unroll
                for (int nt = 0; nt < 8; ++nt)
                    mma16816(acc[mt][nt], af[mt], bf[nt]);
        }
    }

    // ---- cooperative folded-bias compute (reuses smem after mainloop)
    __syncthreads();
    float* smBias = (float*)sm;
    #pragma unroll
    for (int q = tid; q < 256; q += 128) {
        int col = colblk + q;
        float a = cvec[col];
        #pragma unroll
        for (int kg = 0; kg < 8; ++kg) a += bp[kg * 512 + col];
        smBias[q] = a;
    }
    __syncthreads();

    float cs[8][2], cq[8][2];
    if (STAT) {
        #pragma unroll
        for (int nt = 0; nt < 8; ++nt) { cs[nt][0]=cs[nt][1]=cq[nt][0]=cq[nt][1]=0.f; }
    }
    #pragma unroll
    for (int mt = 0; mt < 4; ++mt) {
        int r0 = row0 + mt * 16 + (lane >> 2);
        #pragma unroll
        for (int nt = 0; nt < 8; ++nt) {
            int cloc = wn * 64 + nt * 8 + (lane & 3) * 2;
            int col  = colblk + cloc;
            float b0 = smBias[cloc], b1 = smBias[cloc + 1];
            float v0 = acc[mt][nt][0] + b0;
            float v1 = acc[mt][nt][1] + b1;
            float v2 = acc[mt][nt][2] + b0;
            float v3 = acc[mt][nt][3] + b1;
            if (EPI == 1) {
                v0 = fmaxf(v0, 0.f); v1 = fmaxf(v1, 0.f);
                v2 = fmaxf(v2, 0.f); v3 = fmaxf(v3, 0.f);
            } else if (EPI == 2) {
                v0 = 1.f / (1.f + __expf(-v0));
                v1 = 1.f / (1.f + __expf(-v1));
                v2 = 1.f / (1.f + __expf(-v2));
                v3 = 1.f / (1.f + __expf(-v3));
            }
            if (STAT) {
                cs[nt][0] += v0 + v2;           cs[nt][1] += v1 + v3;
                cq[nt][0] += v0 * v0 + v2 * v2; cq[nt][1] += v1 * v1 + v3 * v3;
            }
            if (OTYPE == 0) {
                __half* C = (__half*)Cout;
                *reinterpret_cast<__half2*>(&C[(size_t)r0 * N + col])       = __floats2half2_rn(v0, v1);
                *reinterpret_cast<__half2*>(&C[(size_t)(r0 + 8) * N + col]) = __floats2half2_rn(v2, v3);
            } else {
                float* C = (float*)Cout;
                *reinterpret_cast<float2*>(&C[(size_t)r0 * N + col])       = make_float2(v0, v1);
                *reinterpret_cast<float2*>(&C[(size_t)(r0 + 8) * N + col]) = make_float2(v2, v3);
            }
        }
    }
    if (STAT) {
        #pragma unroll
        for (int nt = 0; nt < 8; ++nt)
            #pragma unroll
            for (int p = 0; p < 2; ++p) {
                #pragma unroll
                for (int off = 4; off < 32; off <<= 1) {
                    cs[nt][p] += __shfl_xor_sync(0xFFFFFFFF, cs[nt][p], off);
                    cq[nt][p] += __shfl_xor_sync(0xFFFFFFFF, cq[nt][p], off);
                }
            }
        if ((lane >> 2) == 0) {
            #pragma unroll
            for (int nt = 0; nt < 8; ++nt) {
                int col = colblk + wn * 64 + nt * 8 + (lane & 3) * 2;
                part2[(size_t)blockIdx.y * 512 + col]             = cs[nt][0];
                part2[(size_t)blockIdx.y * 512 + col + 1]         = cs[nt][1];
                part2[(size_t)(GY4 + blockIdx.y) * 512 + col]     = cq[nt][0];
                part2[(size_t)(GY4 + blockIdx.y) * 512 + col + 1] = cq[nt][1];
            }
        }
    }
}

// ---------------- launch ----------------
template<typename Tp>
static inline Tp* sym(const void* symbol)
{
    void* p = nullptr;
    cudaGetSymbolAddress(&p, symbol);
    return (Tp*)p;
}

extern "C" void kernel_launch(void* const* d_in, const int* in_sizes, int n_in,
                              void* d_out, int out_size)
{
    const float* x   = (const float*)d_in[0];
    const float* ng0 = (const float*)d_in[1];
    const float* nb0 = (const float*)d_in[2];
    const float* nW0 = (const float*)d_in[3];
    const float* nc0 = (const float*)d_in[4];
    const float* ng1 = (const float*)d_in[5];
    const float* nb1 = (const float*)d_in[6];
    const float* nW1 = (const float*)d_in[7];
    const float* nc1 = (const float*)d_in[8];
    const float* mg0 = (const float*)d_in[9];
    const float* mb0 = (const float*)d_in[10];
    const float* mW0 = (const float*)d_in[11];
    const float* mc0 = (const float*)d_in[12];
    const float* mg1 = (const float*)d_in[13];
    const float* mb1 = (const float*)d_in[14];
    const float* mW1 = (const float*)d_in[15];
    const float* mc1 = (const float*)d_in[16];
    const float* fg0 = (const float*)d_in[17];
    const float* fb0 = (const float*)d_in[18];
    const float* fW0 = (const float*)d_in[19];
    const float* fc0 = (const float*)d_in[20];
    const float* fg1 = (const float*)d_in[21];
    const float* fb1 = (const float*)d_in[22];
    const float* fW1 = (const float*)d_in[23];
    const float* fc1 = (const float*)d_in[24];
    float* out = (float*)d_out;

    __half* xh    = sym<__half>(g_xh);
    __half* XNH   = sym<__half>(g_XNH);
    __half* XNODE = sym<__half>(g_XNODE);
    __half* P     = sym<__half>(g_P);
    __half* Q     = sym<__half>(g_Q);
    __half* XMSG  = sym<__half>(g_XMSG);
    __half* XAGG  = sym<__half>(g_XAGG);
    __half* FH    = sym<__half>(g_FH);
    float*  part  = sym<float >(g_part);
    float*  part2 = sym<float >(g_part2);
    float*  bpart = sym<float >(g_bpart);
    float*  S     = sym<float >(g_sbuf);
    float*  T     = sym<float >(g_tbuf);
    float*  zero  = sym<float >(g_zero);

    __half* Whn0 = sym<__half>(g_Whn0);
    __half* Whn1 = sym<__half>(g_Whn1);
    __half* Whp  = sym<__half>(g_Whp);
    __half* Whq  = sym<__half>(g_Whq);
    __half* Whm1 = sym<__half>(g_Whm1);
    __half* Whf0 = sym<__half>(g_Whf0);
    __half* Whf1 = sym<__half>(g_Whf1);

    // per-stage bias partial slices
    float* bp_n0 = bpart + 0 * 8 * 512;
    float* bp_n1 = bpart + 1 * 8 * 512;
    float* bp_p  = bpart + 2 * 8 * 512;
    float* bp_q  = bpart + 3 * 8 * 512;
    float* bp_m1 = bpart + 4 * 8 * 512;
    float* bp_f0 = bpart + 5 * 8 * 512;
    float* bp_f1 = bpart + 6 * 8 * 512;

    float *s_n0 = S + 0*512, *t_n0 = T + 0*512;
    float *s_n1 = S + 1*512, *t_n1 = T + 1*512;
    float *s_p  = S + 2*512, *t_p  = T + 2*512;
    float *s_q  = S + 3*512, *t_q  = T + 3*512;
    float *s_m1 = S + 4*512, *t_m1 = T + 4*512;
    float *s_f0 = S + 5*512, *t_f0 = T + 5*512;
    float *s_f1 = S + 6*512, *t_f1 = T + 6*512;

    static cudaStream_t sN = nullptr;
    static cudaEvent_t  eF0 = nullptr, eNode = nullptr;
    if (!sN) {
        cudaStreamCreateWithFlags(&sN, cudaStreamNonBlocking);
        cudaEventCreateWithFlags(&eF0,   cudaEventDisableTiming);
        cudaEventCreateWithFlags(&eNode, cudaEventDisableTiming);
        cudaFuncSetAttribute(gemm_h<0,1,0,1>, cudaFuncAttributeMaxDynamicSharedMemorySize, SHM_BYTES);
        cudaFuncSetAttribute(gemm_h<0,2,0,1>, cudaFuncAttributeMaxDynamicSharedMemorySize, SHM_BYTES);
        cudaFuncSetAttribute(gemm_h<0,0,0,0>, cudaFuncAttributeMaxDynamicSharedMemorySize, SHM_BYTES);
        cudaFuncSetAttribute(gemm_h<1,2,0,0>, cudaFuncAttributeMaxDynamicSharedMemorySize, SHM_BYTES);
        cudaFuncSetAttribute(gemm_h<2,1,0,1>, cudaFuncAttributeMaxDynamicSharedMemorySize, SHM_BYTES);
        cudaFuncSetAttribute(gemm_h<0,2,1,0>, cudaFuncAttributeMaxDynamicSharedMemorySize, SHM_BYTES);
    }

    // ---- shared prologue (stream 0)
    cvt_colstats<<<NCHUNK, 256>>>(x, xh, part);
    nk_final_fold3<<<1, 256>>>(part, M4,
        ng0, nb0, s_n0, t_n0,
        mg0, mb0, s_p,  t_p,
        mg0 + 256, mb0 + 256, s_q, t_q);
    cudaEventRecord(eF0, 0);
    cudaStreamWaitEvent(sN, eF0, 0);

    // ---- node branch (stream sN)
    fold_wb<<<dim3(4, 8), 128, 0, sN>>>(nW0, s_n0, t_n0, Whn0, bp_n0, 256, 512);
    gemm_h<0,1,0,1><<<dim3(2, GY4), 128, SHM_BYTES, sN>>>(xh, nullptr, Whn0, nc0, bp_n0, XNH, part2, 256, 512);
    cta_final_fold<<<1, 512, 0, sN>>>(part2, M4, ng1, nb1, s_n1, t_n1);
    fold_wb<<<dim3(2, 8), 128, 0, sN>>>(nW1, s_n1, t_n1, Whn1, bp_n1, 512, 256);
    gemm_h<0,2,0,1><<<dim3(1, GY4), 128, SHM_BYTES, sN>>>(XNH, nullptr, Whn1, nc1, bp_n1, XNODE, part2, 512, 256);
    cta_final_fold<<<1, 256, 0, sN>>>(part2, M4, fg0, fb0, s_f0, t_f0);
    cudaEventRecord(eNode, sN);

    // ---- msg branch (stream 0)
    fold_wb<<<dim3(4, 8), 128>>>(mW0,             s_p, t_p, Whp, bp_p, 256, 512);
    fold_wb<<<dim3(4, 8), 128>>>(mW0 + 256 * 512, s_q, t_q, Whq, bp_q, 256, 512);
    gemm_h<0,0,0,0><<<dim3(2, GY4), 128, SHM_BYTES>>>(xh, nullptr, Whp, zero, bp_p, P, nullptr, 256, 512);
    gemm_h<0,0,0,0><<<dim3(2, GY4), 128, SHM_BYTES>>>(xh, nullptr, Whq, mc0,  bp_q, Q, nullptr, 256, 512);
    pqstats_partial<<<NCHUNK, 512>>>(P, Q, part);
    nk_final_fold<<<1, 512>>>(part, 512, 0, M12, mg1, mb1, s_m1, t_m1);
    fold_wb<<<dim3(2, 8), 128>>>(mW1, s_m1, t_m1, Whm1, bp_m1, 512, 256);
    gemm_h<1,2,0,0><<<dim3(1, M12/64), 128, SHM_BYTES>>>(P, Q, Whm1, mc1, bp_m1, XMSG, nullptr, 512, 256);
    avg3_stats<<<NCHUNK, 256>>>(XMSG, XAGG, part);
    nk_final_fold<<<1, 256>>>(part, 512, 256, M4, fg0 + 256, fb0 + 256, s_f0 + 256, t_f0 + 256);

    // ---- join + final MLP (stream 0)
    cudaStreamWaitEvent(0, eNode, 0);
    fold_wb<<<dim3(4, 8), 128>>>(fW0, s_f0, t_f0, Whf0, bp_f0, 512, 512);
    gemm_h<2,1,0,1><<<dim3(2, GY4), 128, SHM_BYTES>>>(XNODE, XAGG, Whf0, fc0, bp_f0, FH, part2, 512, 512);
    cta_final_fold<<<1, 512>>>(part2, M4, fg1, fb1, s_f1, t_f1);
    fold_wb<<<dim3(2, 8), 128>>>(fW1, s_f1, t_f1, Whf1, bp_f1, 512, 256);
    gemm_h<0,2,1,0><<<dim3(1, GY4), 128, SHM_BYTES>>>(FH, nullptr, Whf1, fc1, bp_f1, out, nullptr, 512, 256);
}